// round 14
// baseline (speedup 1.0000x reference)
#include <cuda_runtime.h>
#include <cuda_bf16.h>
#include <cstdint>
#include <cstddef>

constexpr int kN   = 32;
constexpr int kC   = 256;
constexpr int kC3  = 768;
constexpr int kT   = 64;
constexpr int kV   = 25;
constexpr int kH   = 8;
constexpr int kWIN = 5;
constexpr int kB   = kN * kT;        // 2048 windows
constexpr int kL   = kWIN * kV;      // 125
constexpr int kU   = kB * kV;        // 51200 unique tokens
constexpr int kM1  = kU + 1;         // + pad row
constexpr int kTV  = kT * kV;        // 1600
constexpr int kXN  = kC * kTV;       // 409600
constexpr float kSCALE = 0.17677669529663687f;  // 1/sqrt(32)

// ---------------- scratch ----------------
__device__ __nv_bfloat16 g_nxh [(size_t)kM1 * kC];
__device__ __nv_bfloat16 g_qkvh[(size_t)kM1 * kC3];
__device__ float         g_k   [(size_t)kM1 * kC];
__device__ __nv_bfloat16 g_fh  [(size_t)kU  * kC];
__device__ float         g_xr  [(size_t)kU  * kC];
__device__ __nv_bfloat16 g_mkvh[(size_t)kU  * kC];
__device__ __nv_bfloat16 g_mqh [(size_t)kU  * kC];
__device__ __nv_bfloat16 g_h1h [(size_t)kU  * kC];
__device__ float         g_ql  [(size_t)kM1 * kH];
__device__ __nv_bfloat16 g_twT [65536];
__device__ float         g_tb  [kC];
__device__ __nv_bfloat16 g_wqkvT[(size_t)kC3 * kC];
__device__ __nv_bfloat16 g_wpT [65536];
__device__ __nv_bfloat16 g_w1T [65536];
__device__ __nv_bfloat16 g_w2T [65536];
__device__ float         g_qkvb[kC3];
__device__ float         g_qaw [kC * kH];
__device__ float         g_qab [kH];

__device__ __forceinline__ void stcs_u32(void* p, uint32_t v) {
    asm volatile("st.global.cs.b32 [%0], %1;" :: "l"(p), "r"(v));
}
__device__ __forceinline__ float2 bf2f(uint32_t u) {
    __nv_bfloat162 h = *(__nv_bfloat162*)&u;
    return make_float2(__bfloat162float(h.x), __bfloat162float(h.y));
}
__device__ __forceinline__ uint32_t f2bf2(float a, float b) {
    __nv_bfloat162 h = {__float2bfloat16(a), __float2bfloat16(b)};
    return *(uint32_t*)&h;
}

// ============ prep ============
__global__ void __launch_bounds__(256) k_prep(const float* __restrict__ t_w,
                                              const float* __restrict__ p_w,
                                              const float* __restrict__ t_b,
                                              const float* __restrict__ p_b,
                                              const float* __restrict__ q_w,
                                              const float* __restrict__ k_w,
                                              const float* __restrict__ v_w,
                                              const float* __restrict__ w1,
                                              const float* __restrict__ w2,
                                              const float* __restrict__ q_b,
                                              const float* __restrict__ k_b,
                                              const float* __restrict__ v_b,
                                              const float* __restrict__ qa_w,
                                              const float* __restrict__ qa_b) {
    int bid = blockIdx.x, tid = threadIdx.x;
    if (bid < 257) {
        __shared__ float srow[kC];
        bool isw = (bid < kC);
        srow[tid] = isw ? t_w[(size_t)bid * kC + tid] : t_b[tid];
        __syncthreads();
        float acc = isw ? 0.f : p_b[tid];
#pragma unroll 8
        for (int m = 0; m < kC; m++) acc += srow[m] * p_w[(size_t)m * kC + tid];
        if (isw) g_twT[(size_t)tid * kC + bid] = __float2bfloat16(acc);
        else     g_tb[tid] = acc;
    } else if (bid < 257 + 384) {
        __shared__ float tile[32][33];
        int t = bid - 257;
        int w = t >> 6; t &= 63;
        int k0 = (t >> 3) * 32, n0 = (t & 7) * 32;
        const float* s = (w == 0) ? q_w : (w == 1) ? k_w : (w == 2) ? v_w
                       : (w == 3) ? p_w : (w == 4) ? w1 : w2;
        __nv_bfloat16* dT = (w < 3) ? (g_wqkvT + (size_t)w * 256 * kC)
                          : (w == 3) ? g_wpT : (w == 4) ? g_w1T : g_w2T;
        int tx = tid & 31, ty = tid >> 5;
#pragma unroll
        for (int j = 0; j < 4; j++)
            tile[ty + 8 * j][tx] = s[(size_t)(k0 + ty + 8 * j) * kC + n0 + tx];
        __syncthreads();
#pragma unroll
        for (int j = 0; j < 4; j++)
            dT[(size_t)(n0 + ty + 8 * j) * kC + k0 + tx] = __float2bfloat16(tile[tx][ty + 8 * j]);
    } else if (bid < 257 + 384 + 3) {
        int k = bid - (257 + 384);
        g_qkvb[k * 256 + tid] = (k == 0) ? q_b[tid] : (k == 1) ? k_b[tid] : v_b[tid];
    } else {
        __shared__ float sqa[kC][kH];
        for (int i = tid; i < kC * kH; i += 256) sqa[i >> 3][i & 7] = qa_w[i];
        __syncthreads();
        int c = tid;
        float acc[8] = {};
        const float* qr = q_w + (size_t)c * kC;
#pragma unroll 4
        for (int j = 0; j < kC; j++) {
            float qv = qr[j];
#pragma unroll
            for (int e = 0; e < 8; e++) acc[e] += qv * sqa[j][e];
        }
#pragma unroll
        for (int e = 0; e < 8; e++) g_qaw[c * kH + e] = acc[e];
        if (tid < kH) {
            float a = qa_b[tid];
            for (int j = 0; j < kC; j++) a += q_b[j] * sqa[j][tid];
            g_qab[tid] = a;
        }
    }
}

// ============ LN of unique tokens -> bf16 nx, raw xr (.cs), fused qlog ============
__global__ void __launch_bounds__(256) k_ln_x(const float* __restrict__ x,
                                              const float* __restrict__ g,
                                              const float* __restrict__ b) {
    __shared__ float sx[32][257];
    int tid = threadIdx.x;
    int u0  = blockIdx.x * 32;
    {
        int ur = tid & 31;
        int u  = u0 + ur;
        int cb = tid >> 5;
        bool has = (u < kU);
        size_t base = 0;
        if (has) { int n = u / kTV; base = (size_t)n * kXN + (u - n * kTV); }
#pragma unroll
        for (int j = 0; j < 32; j++) {
            int c = cb * 32 + j;
            sx[ur][c] = has ? x[base + (size_t)c * kTV] : 0.f;
        }
    }
    __syncthreads();
    int lane = tid & 31, warp = tid >> 5;
    float wreg[8][8];
#pragma unroll
    for (int j = 0; j < 8; j++) {
        const float4* wr = (const float4*)(g_qaw + (size_t)(lane + 32 * j) * kH);
        float4 w0 = wr[0], w1 = wr[1];
        wreg[j][0] = w0.x; wreg[j][1] = w0.y; wreg[j][2] = w0.z; wreg[j][3] = w0.w;
        wreg[j][4] = w1.x; wreg[j][5] = w1.y; wreg[j][6] = w1.z; wreg[j][7] = w1.w;
    }
    float qab = (lane < kH) ? g_qab[lane] : 0.f;
#pragma unroll 1
    for (int rr = 0; rr < 4; rr++) {
        int ur = warp * 4 + rr;
        int u  = u0 + ur;
        if (u >= kM1) continue;
        float vals[8];
        float s = 0.f, sq = 0.f;
#pragma unroll
        for (int j = 0; j < 8; j++) {
            float t = sx[ur][lane + 32 * j];
            vals[j] = t; s += t; sq += t * t;
        }
#pragma unroll
        for (int o = 16; o; o >>= 1) {
            s  += __shfl_xor_sync(0xffffffffu, s,  o);
            sq += __shfl_xor_sync(0xffffffffu, sq, o);
        }
        float mean = s * (1.f / kC);
        float var  = sq * (1.f / kC) - mean * mean;
        float rstd = rsqrtf(var + 1e-5f);
        float acc[8] = {};
#pragma unroll
        for (int j = 0; j < 8; j++) {
            int c = lane + 32 * j;
            float nv = (vals[j] - mean) * rstd * g[c] + b[c];
            g_nxh[(size_t)u * kC + c] = __float2bfloat16(nv);
            if (u < kU) __stcs(g_xr + (size_t)u * kC + c, vals[j]);
#pragma unroll
            for (int e = 0; e < 8; e++) acc[e] += nv * wreg[j][e];
        }
#pragma unroll
        for (int o = 16; o; o >>= 1)
#pragma unroll
            for (int e = 0; e < 8; e++)
                acc[e] += __shfl_xor_sync(0xffffffffu, acc[e], o);
        if (lane < kH) g_ql[(size_t)u * kH + lane] = (acc[lane] + qab) * kSCALE;
    }
}

// ============ bf16 GEMM (unchanged from R13) ============
constexpr int HP   = 40;
constexpr int ASZH = 128 * HP;
constexpr int BSZH = 256 * HP;
constexpr int GEMM_SMEM = 3 * (ASZH + BSZH) * 2;
constexpr int BPITCH = 264;

__device__ __forceinline__ void mma_bf16(float (&d)[4], const uint32_t (&a)[4],
                                         const uint32_t (&bb)[2]) {
    asm volatile(
        "mma.sync.aligned.m16n8k16.row.col.f32.bf16.bf16.f32 "
        "{%0,%1,%2,%3}, {%4,%5,%6,%7}, {%8,%9}, {%0,%1,%2,%3};\n"
        : "+f"(d[0]), "+f"(d[1]), "+f"(d[2]), "+f"(d[3])
        : "r"(a[0]), "r"(a[1]), "r"(a[2]), "r"(a[3]), "r"(bb[0]), "r"(bb[1]));
}
__device__ __forceinline__ void cpa16(uint32_t dst, const void* src, bool pred) {
    int sz = pred ? 16 : 0;
    asm volatile("cp.async.cg.shared.global [%0], [%1], 16, %2;\n"
                 :: "r"(dst), "l"(src), "r"(sz));
}
__device__ __forceinline__ float gelu_exact(float x) {
    return 0.5f * x * (1.0f + erff(x * 0.70710678118654752f));
}

template<int EPI, int NPAIR>
__global__ void __launch_bounds__(512, 1) k_gemm7(const __nv_bfloat16* __restrict__ A1,
                                                  const __nv_bfloat16* __restrict__ W1,
                                                  const __nv_bfloat16* __restrict__ A2,
                                                  const __nv_bfloat16* __restrict__ W2,
                                                  const float* __restrict__ bias,
                                                  const float* __restrict__ addm,
                                                  float* __restrict__ D,
                                                  __nv_bfloat16* __restrict__ Dh,
                                                  const float* __restrict__ lng,
                                                  const float* __restrict__ lnb,
                                                  int M, int ldD) {
    extern __shared__ char smc[];
    __nv_bfloat16* As = (__nv_bfloat16*)smc;
    __nv_bfloat16* Bs = As + 3 * ASZH;
    float* ep = (float*)smc;
    uint32_t sA = (uint32_t)__cvta_generic_to_shared(As);
    uint32_t sB = (uint32_t)__cvta_generic_to_shared(Bs);

    int coly = blockIdx.y * 256;
    bias += coly;
    if (D)  D  += coly;
    if (Dh) Dh += coly;

    int tid = threadIdx.x, lane = tid & 31, warp = tid >> 5;
    int wm = warp >> 2, wn = warp & 3;
    int p = lane >> 2, q = lane & 3;
    int row0 = blockIdx.x * 128;
    int mbase = wm * 32, nbase = wn * 64;

    int ar = tid & 127, ah = tid >> 7;
    int bn = tid & 255, bh = tid >> 8;
    bool arow_ok = (row0 + ar) < M;
    const __nv_bfloat16* A1g = A1 + (size_t)(row0 + ar) * kC + ah * 8;
    const __nv_bfloat16* W1g = W1 + (size_t)(coly + bn) * kC + bh * 16;
    const __nv_bfloat16* A2g = (NPAIR == 2) ? (A2 + (size_t)(row0 + ar) * kC + ah * 8) : A1g;
    const __nv_bfloat16* W2g = (NPAIR == 2) ? (W2 + (size_t)(coly + bn) * kC + bh * 16) : W1g;
    uint32_t adst0 = sA + (uint32_t)((ar * HP + ah * 8) * 2);
    uint32_t bdst0 = sB + (uint32_t)((bn * HP + bh * 16) * 2);

    auto issue = [&](int kt) {
        int ktt = kt & 7;
        int buf = kt % 3;
        const __nv_bfloat16* as = ((NPAIR == 2 && (kt >> 3)) ? A2g : A1g) + ktt * 32;
        const __nv_bfloat16* bs = ((NPAIR == 2 && (kt >> 3)) ? W2g : W1g) + ktt * 32;
        cpa16(adst0 + (uint32_t)(buf * ASZH * 2), as, arow_ok);
        uint32_t bd = bdst0 + (uint32_t)(buf * BSZH * 2);
        cpa16(bd,      bs,     true);
        cpa16(bd + 16, bs + 8, true);
    };

    float acc[2][8][4] = {};
    const int TOT = 8 * NPAIR;

    issue(0);
    asm volatile("cp.async.commit_group;\n");
    issue(1);
    asm volatile("cp.async.commit_group;\n");

#pragma unroll 1
    for (int kt = 0; kt < TOT; kt++) {
        if (kt < TOT - 1) asm volatile("cp.async.wait_group 1;\n");
        else              asm volatile("cp.async.wait_group 0;\n");
        __syncthreads();
        if (kt + 2 < TOT) {
            issue(kt + 2);
            asm volatile("cp.async.commit_group;\n");
        }
        int buf = kt % 3;
        const __nv_bfloat16* Ab = As + buf * ASZH;
        const __nv_bfloat16* Bb = Bs + buf * BSZH;
#pragma unroll
        for (int kk = 0; kk < 32; kk += 16) {
            uint32_t af[2][4], bf[8][2];
#pragma unroll
            for (int mi = 0; mi < 2; mi++) {
                const __nv_bfloat16* a0 = Ab + (mbase + mi * 16 + p) * HP + kk + 2 * q;
                af[mi][0] = *(const uint32_t*)(a0);
                af[mi][1] = *(const uint32_t*)(a0 + 8 * HP);
                af[mi][2] = *(const uint32_t*)(a0 + 8);
                af[mi][3] = *(const uint32_t*)(a0 + 8 * HP + 8);
            }
#pragma unroll
            for (int ni = 0; ni < 8; ni++) {
                const __nv_bfloat16* b0 = Bb + (nbase + ni * 8 + p) * HP + kk + 2 * q;
                bf[ni][0] = *(const uint32_t*)(b0);
                bf[ni][1] = *(const uint32_t*)(b0 + 8);
            }
#pragma unroll
            for (int mi = 0; mi < 2; mi++)
#pragma unroll
                for (int ni = 0; ni < 8; ni++)
                    mma_bf16(acc[mi][ni], af[mi], bf[ni]);
        }
    }
    __syncthreads();

    if (EPI == 0 || EPI == 2) {
#pragma unroll
        for (int mi = 0; mi < 2; mi++) {
            int r1 = row0 + mbase + mi * 16 + p;
            int r2 = r1 + 8;
#pragma unroll
            for (int ni = 0; ni < 8; ni++) {
                int cc = nbase + ni * 8 + 2 * q;
                float2 bv = *(const float2*)(bias + cc);
                float d0 = acc[mi][ni][0] + bv.x, d1 = acc[mi][ni][1] + bv.y;
                float d2 = acc[mi][ni][2] + bv.x, d3 = acc[mi][ni][3] + bv.y;
                if (EPI == 2) {
                    d0 = gelu_exact(d0); d1 = gelu_exact(d1);
                    d2 = gelu_exact(d2); d3 = gelu_exact(d3);
                }
                __nv_bfloat162 o1 = {__float2bfloat16(d0), __float2bfloat16(d1)};
                __nv_bfloat162 o2 = {__float2bfloat16(d2), __float2bfloat16(d3)};
                if (r1 < M) *(__nv_bfloat162*)(Dh + (size_t)r1 * ldD + cc) = o1;
                if (r2 < M) *(__nv_bfloat162*)(Dh + (size_t)r2 * ldD + cc) = o2;
            }
        }
    } else {
#pragma unroll 1
        for (int half = 0; half < 2; half++) {
            __syncthreads();
            if ((wm >> 1) == half) {
#pragma unroll
                for (int mi = 0; mi < 2; mi++) {
                    int lr1 = mbase + mi * 16 + p;
                    int lr2 = lr1 + 8;
                    int r1 = row0 + lr1, r2 = row0 + lr2;
                    int e1 = lr1 - half * 64, e2 = lr2 - half * 64;
#pragma unroll
                    for (int ni = 0; ni < 8; ni++) {
                        int cc = nbase + ni * 8 + 2 * q;
                        float2 bv = *(const float2*)(bias + cc);
                        float2 a1 = *(const float2*)(addm + (size_t)r1 * kC + cc);
                        float2 a2 = *(const float2*)(addm + (size_t)r2 * kC + cc);
                        float2 o1 = {acc[mi][ni][0] + bv.x + a1.x, acc[mi][ni][1] + bv.y + a1.y};
                        float2 o2 = {acc[mi][ni][2] + bv.x + a2.x, acc[mi][ni][3] + bv.y + a2.y};
                        if (EPI == 3) {
                            *(float2*)(D + (size_t)r1 * ldD + cc) = o1;
                            *(float2*)(D + (size_t)r2 * ldD + cc) = o2;
                        }
                        *(float2*)(ep + e1 * BPITCH + cc) = o1;
                        *(float2*)(ep + e2 * BPITCH + cc) = o2;
                    }
                }
            }
            __syncthreads();
            if (EPI == 3) {
                float gg[8], bb[8];
#pragma unroll
                for (int j = 0; j < 8; j++) {
                    int c = lane + 32 * j;
                    gg[j] = lng[c]; bb[j] = lnb[c];
                }
#pragma unroll
                for (int rr = 0; rr < 4; rr++) {
                    int lr = warp * 4 + rr;
                    float vals[8]; float s = 0.f, sq = 0.f;
#pragma unroll
                    for (int j = 0; j < 8; j++) {
                        float t = ep[lr * BPITCH + lane + 32 * j];
                        vals[j] = t; s += t; sq += t * t;
                    }
#pragma unroll
                    for (int o = 16; o; o >>= 1) {
                        s  += __shfl_xor_sync(0xffffffffu, s,  o);
                        sq += __shfl_xor_sync(0xffffffffu, sq, o);
                    }
                    float mean = s * (1.f / kC);
                    float var  = sq * (1.f / kC) - mean * mean;
                    float rstd = rsqrtf(var + 1e-5f);
                    int gr = row0 + half * 64 + lr;
#pragma unroll
                    for (int j = 0; j < 8; j++) {
                        int c = lane + 32 * j;
                        Dh[(size_t)gr * kC + c] = __float2bfloat16((vals[j] - mean) * rstd * gg[j] + bb[j]);
                    }
                }
            } else {
#pragma unroll 1
                for (int it = 0; it < 32; it++) {
                    int j = it * 512 + tid;
                    int c = j >> 6, rr = j & 63;
                    unsigned R = (unsigned)(row0 + half * 64 + rr);
                    unsigned b = R / 25u;
                    unsigned v = R - b * 25u;
                    unsigned n = b >> 6, t = b & 63u;
                    D[(size_t)n * kXN + (size_t)c * kTV + t * kV + v] = ep[rr * BPITCH + c];
                }
            }
        }
    }
}

// ============ pool v6: 4 windows/CTA (one n), smem-staged contiguous slices ============
constexpr int TW    = 4;
constexpr int SROWS = (TW + 4) * kV;     // 200 rows per stage
constexpr int KAP   = 12;
// dynamic smem layout (floats after the bf16 stage):
constexpr int PS_STAGE_B = SROWS * kC * 2;               // 102400 bytes
constexpr int PS_SQW  = 0;                                // [TW][8][128]
constexpr int PS_SKW  = PS_SQW + TW * kH * 128;
constexpr int PS_SPQ  = PS_SKW + TW * kH * 128;           // [TW][256]
constexpr int PS_SKAW = PS_SPQ + TW * kC;
constexpr int PS_SRED = PS_SKAW + kC * KAP;               // [TW][4][8][9]
constexpr int PS_FLOATS = PS_SRED + TW * 4 * kH * 9;
constexpr int POOL_SMEM = PS_STAGE_B + PS_FLOATS * 4;     // ~156 KB

__global__ void __launch_bounds__(512, 1) k_pool(const float* __restrict__ ka_w,
                                                 const float* __restrict__ ka_b) {
    extern __shared__ char psm[];
    __nv_bfloat16* stage = (__nv_bfloat16*)psm;
    float* fsm  = (float*)(psm + PS_STAGE_B);
    float* sqw  = fsm + PS_SQW;
    float* skw  = fsm + PS_SKW;
    float* spq  = fsm + PS_SPQ;
    float* skaw = fsm + PS_SKAW;
    float* sred = fsm + PS_SRED;
    uint32_t stAddr = (uint32_t)__cvta_generic_to_shared(stage);

    int tid = threadIdx.x, lane = tid & 31;
    int ww = tid >> 7;                 // window in tile 0..3
    int ti = tid & 127;                // channel-pair 0..127
    int wq = ti >> 5;                  // warp-in-window 0..3
    int hch = ti >> 4;                 // head of channels 2ti,2ti+1
    int b0 = blockIdx.x * TW;
    int n = b0 / kT, t0 = b0 % kT;
    int b = b0 + ww, t = t0 + ww;

    for (int i = tid; i < kC * kH; i += 512) {
        int c = i >> 3, e = i & 7;
        skaw[c * KAP + e] = ka_w[i];
    }
    float kab = (lane < kH) ? ka_b[lane] : 0.f;

    // ---- q-weight softmax: window ww, warp wq -> heads 2wq, 2wq+1 ----
#pragma unroll
    for (int hi = 0; hi < 2; hi++) {
        int hh = 2 * wq + hi;
        float lv[4]; float mx = -1e30f;
#pragma unroll
        for (int i = 0; i < 4; i++) {
            int l = lane + 32 * i;
            float val = -1e30f;
            if (l < kL) {
                int w = l / kV, v = l - w * kV;
                int tp = t + w - 2;
                size_t gid = (tp >= 0 && tp < kT) ? (size_t)(n * kT + tp) * kV + v : (size_t)kU;
                val = g_ql[gid * kH + hh];
            }
            lv[i] = val; mx = fmaxf(mx, val);
        }
#pragma unroll
        for (int o = 16; o; o >>= 1) mx = fmaxf(mx, __shfl_xor_sync(0xffffffffu, mx, o));
        float sm = 0.f;
#pragma unroll
        for (int i = 0; i < 4; i++) {
            int l = lane + 32 * i;
            lv[i] = (l < kL) ? expf(lv[i] - mx) : 0.f;
            sm += lv[i];
        }
#pragma unroll
        for (int o = 16; o; o >>= 1) sm += __shfl_xor_sync(0xffffffffu, sm, o);
        float inv = 1.f / sm;
#pragma unroll
        for (int i = 0; i < 4; i++) {
            int l = lane + 32 * i;
            if (l < kL) sqw[(ww * kH + hh) * 128 + l] = lv[i] * inv;
        }
    }

    // ---- slice stager: contiguous 200-row block, OOB t -> pad row ----
    auto stage_slice = [&](int slice) {
        __syncthreads();   // all readers of previous stage done
#pragma unroll 1
        for (int it = tid; it < SROWS * 32; it += 512) {
            int r = it >> 5, c16 = it & 31;
            int tp = t0 - 2 + r / kV;
            int v  = r % kV;
            size_t gid = (tp >= 0 && tp < kT) ? (size_t)(n * kT + tp) * kV + v : (size_t)kU;
            const __nv_bfloat16* src = g_qkvh + gid * kC3 + slice * 256 + c16 * 8;
            cpa16(stAddr + (uint32_t)((r * kC + c16 * 8) * 2), src, true);
        }
        asm volatile("cp.async.commit_group;\n");
        asm volatile("cp.async.wait_group 0;\n");
        __syncthreads();
    };

    // ---- stage q; pass A: pq + mq ----
    stage_slice(0);
    float pq0 = 0.f, pq1 = 0.f;
#pragma unroll 5
    for (int v = 0; v < kV; v++) {
        float a0 = 0.f, a1 = 0.f;
#pragma unroll
        for (int w = 0; w < kWIN; w++) {
            int sr = (ww + w) * kV + v;
            float2 xv = bf2f(*(const uint32_t*)(stage + sr * kC + 2 * ti));
            float sw = sqw[(ww * kH + hch) * 128 + w * kV + v];
            pq0 += sw * xv.x; pq1 += sw * xv.y;
            a0 += xv.x; a1 += xv.y;
        }
        stcs_u32(g_mqh + ((size_t)b * kV + v) * kC + 2 * ti, f2bf2(a0 * 0.2f, a1 * 0.2f));
    }
    spq[ww * kC + 2 * ti]     = pq0;
    spq[ww * kC + 2 * ti + 1] = pq1;

    // ---- stage k; pass B: k logits ----
    stage_slice(1);
#pragma unroll 1
    for (int l = wq; l < kL; l += 4) {
        int w = l / kV, v = l - w * kV;
        const __nv_bfloat16* kr = stage + ((ww + w) * kV + v) * kC;
        float acc[8] = {};
#pragma unroll
        for (int j = 0; j < 4; j++) {
            int c0 = 2 * (lane + 32 * j);
            float2 kv = bf2f(*(const uint32_t*)(kr + c0));
            float2 pq2 = *(const float2*)(spq + ww * kC + c0);
            float kp0 = kv.x * pq2.x;
            float kp1 = kv.y * pq2.y;
            const float4* ka0 = (const float4*)(skaw + c0 * KAP);
            const float4* ka1 = (const float4*)(skaw + (c0 + 1) * KAP);
            float4 a0 = ka0[0], a1 = ka0[1], b0f = ka1[0], b1f = ka1[1];
            acc[0] += kp0 * a0.x + kp1 * b0f.x; acc[1] += kp0 * a0.y + kp1 * b0f.y;
            acc[2] += kp0 * a0.z + kp1 * b0f.z; acc[3] += kp0 * a0.w + kp1 * b0f.w;
            acc[4] += kp0 * a1.x + kp1 * b1f.x; acc[5] += kp0 * a1.y + kp1 * b1f.y;
            acc[6] += kp0 * a1.z + kp1 * b1f.z; acc[7] += kp0 * a1.w + kp1 * b1f.w;
        }
#pragma unroll
        for (int o = 16; o >= 8; o >>= 1)
#pragma unroll
            for (int e = 0; e < 8; e++)
                acc[e] += __shfl_xor_sync(0xffffffffu, acc[e], o);
        float* sr8 = sred + ((ww * 4 + wq) * kH) * 9;
        if (lane < 8) {
#pragma unroll
            for (int e = 0; e < 8; e++) sr8[lane * 9 + e] = acc[e];
        }
        __syncwarp();
        if (lane < 8) {
            float s2 = 0.f;
#pragma unroll
            for (int m = 0; m < 8; m++) s2 += sr8[m * 9 + lane];
            skw[(ww * kH + lane) * 128 + l] = (s2 + kab) * kSCALE;
        }
        __syncwarp();
    }
    __syncthreads();

    // ---- k-weight softmax ----
#pragma unroll
    for (int hi = 0; hi < 2; hi++) {
        int hh = 2 * wq + hi;
        float lv[4]; float mx = -1e30f;
#pragma unroll
        for (int i = 0; i < 4; i++) {
            int l = lane + 32 * i;
            lv[i] = (l < kL) ? skw[(ww * kH + hh) * 128 + l] : -1e30f;
            mx = fmaxf(mx, lv[i]);
        }
#pragma unroll
        for (int o = 16; o; o >>= 1) mx = fmaxf(mx, __shfl_xor_sync(0xffffffffu, mx, o));
        float sm = 0.f;
#pragma unroll
        for (int i = 0; i < 4; i++) {
            int l = lane + 32 * i;
            lv[i] = (l < kL) ? expf(lv[i] - mx) : 0.f;
            sm += lv[i];
        }
#pragma unroll
        for (int o = 16; o; o >>= 1) sm += __shfl_xor_sync(0xffffffffu, sm, o);
        float inv = 1.f / sm;
#pragma unroll
        for (int i = 0; i < 4; i++) {
            int l = lane + 32 * i;
            if (l < kL) skw[(ww * kH + hh) * 128 + l] = lv[i] * inv;
        }
    }
    __syncthreads();

    // ---- pass C1: pk from staged k ----
    float pk0 = 0.f, pk1 = 0.f;
#pragma unroll 5
    for (int v = 0; v < kV; v++) {
#pragma unroll
        for (int w = 0; w < kWIN; w++) {
            int sr = (ww + w) * kV + v;
            float2 kv = bf2f(*(const uint32_t*)(stage + sr * kC + 2 * ti));
            float sw = skw[(ww * kH + hch) * 128 + w * kV + v];
            pk0 += sw * kv.x;
            pk1 += sw * kv.y;
        }
    }

    // ---- stage v; pass C2: mkv = pk * mean(v) ----
    stage_slice(2);
#pragma unroll 5
    for (int v = 0; v < kV; v++) {
        float a0 = 0.f, a1 = 0.f;
#pragma unroll
        for (int w = 0; w < kWIN; w++) {
            int sr = (ww + w) * kV + v;
            float2 vv = bf2f(*(const uint32_t*)(stage + sr * kC + 2 * ti));
            a0 += vv.x;
            a1 += vv.y;
        }
        stcs_u32(g_mkvh + ((size_t)b * kV + v) * kC + 2 * ti,
                 f2bf2(pk0 * a0 * 0.2f, pk1 * a1 * 0.2f));
    }
}

// ===================================================================================
extern "C" void kernel_launch(void* const* d_in, const int* in_sizes, int n_in,
                              void* d_out, int out_size) {
    const float* x    = (const float*)d_in[0];
    const float* ln1g = (const float*)d_in[1];
    const float* ln1b = (const float*)d_in[2];
    const float* q_w  = (const float*)d_in[3];
    const float* q_b  = (const float*)d_in[4];
    const float* qa_w = (const float*)d_in[5];
    const float* qa_b = (const float*)d_in[6];
    const float* k_w  = (const float*)d_in[7];
    const float* k_b  = (const float*)d_in[8];
    const float* ka_w = (const float*)d_in[9];
    const float* ka_b = (const float*)d_in[10];
    const float* v_w  = (const float*)d_in[11];
    const float* v_b  = (const float*)d_in[12];
    const float* t_w  = (const float*)d_in[13];
    const float* t_b  = (const float*)d_in[14];
    const float* p_w  = (const float*)d_in[15];
    const float* p_b  = (const float*)d_in[16];
    const float* ffng = (const float*)d_in[17];
    const float* ffnb = (const float*)d_in[18];
    const float* w1   = (const float*)d_in[19];
    const float* b1   = (const float*)d_in[20];
    const float* w2   = (const float*)d_in[21];
    const float* b2   = (const float*)d_in[22];
    float* out = (float*)d_out;

    float *p_k, *p_xr, *p_tb, *p_qkvb;
    __nv_bfloat16 *p_nxh, *p_qkvh, *p_fh, *p_mkvh, *p_mqh, *p_h1h, *p_twT, *p_wqkvT, *p_wpT, *p_w1T, *p_w2T;
    cudaGetSymbolAddress((void**)&p_k,     g_k);
    cudaGetSymbolAddress((void**)&p_xr,    g_xr);
    cudaGetSymbolAddress((void**)&p_tb,    g_tb);
    cudaGetSymbolAddress((void**)&p_qkvb,  g_qkvb);
    cudaGetSymbolAddress((void**)&p_nxh,   g_nxh);
    cudaGetSymbolAddress((void**)&p_qkvh,  g_qkvh);
    cudaGetSymbolAddress((void**)&p_fh,    g_fh);
    cudaGetSymbolAddress((void**)&p_mkvh,  g_mkvh);
    cudaGetSymbolAddress((void**)&p_mqh,   g_mqh);
    cudaGetSymbolAddress((void**)&p_h1h,   g_h1h);
    cudaGetSymbolAddress((void**)&p_twT,   g_twT);
    cudaGetSymbolAddress((void**)&p_wqkvT, g_wqkvT);
    cudaGetSymbolAddress((void**)&p_wpT,   g_wpT);
    cudaGetSymbolAddress((void**)&p_w1T,   g_w1T);
    cudaGetSymbolAddress((void**)&p_w2T,   g_w2T);

    cudaFuncSetAttribute(k_gemm7<0,1>, cudaFuncAttributeMaxDynamicSharedMemorySize, GEMM_SMEM);
    cudaFuncSetAttribute(k_gemm7<2,1>, cudaFuncAttributeMaxDynamicSharedMemorySize, GEMM_SMEM);
    cudaFuncSetAttribute(k_gemm7<3,2>, cudaFuncAttributeMaxDynamicSharedMemorySize, GEMM_SMEM);
    cudaFuncSetAttribute(k_gemm7<4,1>, cudaFuncAttributeMaxDynamicSharedMemorySize, GEMM_SMEM);
    cudaFuncSetAttribute(k_pool,       cudaFuncAttributeMaxDynamicSharedMemorySize, POOL_SMEM);

    dim3 gqkv((kM1 + 127) / 128, 3);   // 401 x 3
    int g2 = kU / 128;                 // 400

    // 0) prep
    k_prep<<<257 + 384 + 3 + 1, 256>>>(t_w, p_w, t_b, p_b, q_w, k_w, v_w, w1, w2,
                                       q_b, k_b, v_b, qa_w, qa_b);
    // 1) LN -> bf16 nx + fp32 xr + fused qlog
    k_ln_x<<<(kM1 + 31) / 32, 256>>>(x, ln1g, ln1b);
    // 2) fused q|k|v projection -> g_qkvh bf16
    k_gemm7<0,1><<<gqkv, 512, GEMM_SMEM>>>(p_nxh, p_wqkvT, nullptr, nullptr, p_qkvb, nullptr,
                                           nullptr, p_qkvh, nullptr, nullptr, kM1, kC3);
    // 3) pooling v6: 4 windows/CTA, smem staging
    k_pool<<<kB / TW, 512, POOL_SMEM>>>(ka_w, ka_b);
    // 4) attraw = mkv@tp_w + mq@p_w + tp_b + xr -> g_k ; fused LN -> f bf16
    k_gemm7<3,2><<<g2, 512, GEMM_SMEM>>>(p_mkvh, p_twT, p_mqh, p_wpT, p_tb, p_xr,
                                         p_k, p_fh, ffng, ffnb, kU, kC);
    // 5) h1 = gelu(f @ w1 + b1) -> bf16
    k_gemm7<2,1><<<g2, 512, GEMM_SMEM>>>(p_fh, p_w1T, nullptr, nullptr, b1, nullptr,
                                         nullptr, p_h1h, nullptr, nullptr, kU, kC);
    // 6) y = h1 @ w2 + b2 + attraw -> transposed out
    k_gemm7<4,1><<<g2, 512, GEMM_SMEM>>>(p_h1h, p_w2T, nullptr, nullptr, b2, p_k,
                                         out, nullptr, nullptr, nullptr, kU, kC);
}

// round 15
// speedup vs baseline: 1.0211x; 1.0211x over previous
#include <cuda_runtime.h>
#include <cuda_bf16.h>
#include <cstdint>
#include <cstddef>

constexpr int kN   = 32;
constexpr int kC   = 256;
constexpr int kC3  = 768;
constexpr int kT   = 64;
constexpr int kV   = 25;
constexpr int kH   = 8;
constexpr int kWIN = 5;
constexpr int kB   = kN * kT;        // 2048 windows
constexpr int kL   = kWIN * kV;      // 125
constexpr int kU   = kB * kV;        // 51200 unique tokens
constexpr int kM1  = kU + 1;         // + pad row
constexpr int kTV  = kT * kV;        // 1600
constexpr int kXN  = kC * kTV;       // 409600
constexpr float kSCALE = 0.17677669529663687f;  // 1/sqrt(32)

// ---------------- scratch ----------------
__device__ __nv_bfloat16 g_nxh [(size_t)kM1 * kC];
__device__ __nv_bfloat16 g_qkvh[(size_t)kM1 * kC3];
__device__ float         g_k   [(size_t)kM1 * kC];
__device__ __nv_bfloat16 g_fh  [(size_t)kU  * kC];
__device__ float         g_xr  [(size_t)kU  * kC];
__device__ __nv_bfloat16 g_mkvh[(size_t)kU  * kC];
__device__ __nv_bfloat16 g_mqh [(size_t)kU  * kC];
__device__ __nv_bfloat16 g_h1h [(size_t)kU  * kC];
__device__ float         g_ql  [(size_t)kM1 * kH];
__device__ float         g_pk  [(size_t)kB  * kC];   // softmax-pooled k per window
__device__ __nv_bfloat16 g_twT [65536];
__device__ float         g_tb  [kC];
__device__ __nv_bfloat16 g_wqkvT[(size_t)kC3 * kC];
__device__ __nv_bfloat16 g_wpT [65536];
__device__ __nv_bfloat16 g_w1T [65536];
__device__ __nv_bfloat16 g_w2T [65536];
__device__ float         g_qkvb[kC3];
__device__ float         g_qaw [kC * kH];
__device__ float         g_qab [kH];

__device__ __forceinline__ void stcs_u32(void* p, uint32_t v) {
    asm volatile("st.global.cs.b32 [%0], %1;" :: "l"(p), "r"(v));
}
__device__ __forceinline__ float2 bf2f(uint32_t u) {
    __nv_bfloat162 h = *(__nv_bfloat162*)&u;
    return make_float2(__bfloat162float(h.x), __bfloat162float(h.y));
}
__device__ __forceinline__ uint32_t f2bf2(float a, float b) {
    __nv_bfloat162 h = {__float2bfloat16(a), __float2bfloat16(b)};
    return *(uint32_t*)&h;
}

// ============ prep ============
__global__ void __launch_bounds__(256) k_prep(const float* __restrict__ t_w,
                                              const float* __restrict__ p_w,
                                              const float* __restrict__ t_b,
                                              const float* __restrict__ p_b,
                                              const float* __restrict__ q_w,
                                              const float* __restrict__ k_w,
                                              const float* __restrict__ v_w,
                                              const float* __restrict__ w1,
                                              const float* __restrict__ w2,
                                              const float* __restrict__ q_b,
                                              const float* __restrict__ k_b,
                                              const float* __restrict__ v_b,
                                              const float* __restrict__ qa_w,
                                              const float* __restrict__ qa_b) {
    int bid = blockIdx.x, tid = threadIdx.x;
    if (bid < 257) {
        __shared__ float srow[kC];
        bool isw = (bid < kC);
        srow[tid] = isw ? t_w[(size_t)bid * kC + tid] : t_b[tid];
        __syncthreads();
        float acc = isw ? 0.f : p_b[tid];
#pragma unroll 8
        for (int m = 0; m < kC; m++) acc += srow[m] * p_w[(size_t)m * kC + tid];
        if (isw) g_twT[(size_t)tid * kC + bid] = __float2bfloat16(acc);
        else     g_tb[tid] = acc;
    } else if (bid < 257 + 384) {
        __shared__ float tile[32][33];
        int t = bid - 257;
        int w = t >> 6; t &= 63;
        int k0 = (t >> 3) * 32, n0 = (t & 7) * 32;
        const float* s = (w == 0) ? q_w : (w == 1) ? k_w : (w == 2) ? v_w
                       : (w == 3) ? p_w : (w == 4) ? w1 : w2;
        __nv_bfloat16* dT = (w < 3) ? (g_wqkvT + (size_t)w * 256 * kC)
                          : (w == 3) ? g_wpT : (w == 4) ? g_w1T : g_w2T;
        int tx = tid & 31, ty = tid >> 5;
#pragma unroll
        for (int j = 0; j < 4; j++)
            tile[ty + 8 * j][tx] = s[(size_t)(k0 + ty + 8 * j) * kC + n0 + tx];
        __syncthreads();
#pragma unroll
        for (int j = 0; j < 4; j++)
            dT[(size_t)(n0 + ty + 8 * j) * kC + k0 + tx] = __float2bfloat16(tile[tx][ty + 8 * j]);
    } else if (bid < 257 + 384 + 3) {
        int k = bid - (257 + 384);
        g_qkvb[k * 256 + tid] = (k == 0) ? q_b[tid] : (k == 1) ? k_b[tid] : v_b[tid];
    } else {
        __shared__ float sqa[kC][kH];
        for (int i = tid; i < kC * kH; i += 256) sqa[i >> 3][i & 7] = qa_w[i];
        __syncthreads();
        int c = tid;
        float acc[8] = {};
        const float* qr = q_w + (size_t)c * kC;
#pragma unroll 4
        for (int j = 0; j < kC; j++) {
            float qv = qr[j];
#pragma unroll
            for (int e = 0; e < 8; e++) acc[e] += qv * sqa[j][e];
        }
#pragma unroll
        for (int e = 0; e < 8; e++) g_qaw[c * kH + e] = acc[e];
        if (tid < kH) {
            float a = qa_b[tid];
            for (int j = 0; j < kC; j++) a += q_b[j] * sqa[j][tid];
            g_qab[tid] = a;
        }
    }
}

// ============ LN of unique tokens -> bf16 nx, raw xr (.cs), fused qlog ============
__global__ void __launch_bounds__(256) k_ln_x(const float* __restrict__ x,
                                              const float* __restrict__ g,
                                              const float* __restrict__ b) {
    __shared__ float sx[32][257];
    int tid = threadIdx.x;
    int u0  = blockIdx.x * 32;
    {
        int ur = tid & 31;
        int u  = u0 + ur;
        int cb = tid >> 5;
        bool has = (u < kU);
        size_t base = 0;
        if (has) { int n = u / kTV; base = (size_t)n * kXN + (u - n * kTV); }
#pragma unroll
        for (int j = 0; j < 32; j++) {
            int c = cb * 32 + j;
            sx[ur][c] = has ? x[base + (size_t)c * kTV] : 0.f;
        }
    }
    __syncthreads();
    int lane = tid & 31, warp = tid >> 5;
    float wreg[8][8];
#pragma unroll
    for (int j = 0; j < 8; j++) {
        const float4* wr = (const float4*)(g_qaw + (size_t)(lane + 32 * j) * kH);
        float4 w0 = wr[0], w1 = wr[1];
        wreg[j][0] = w0.x; wreg[j][1] = w0.y; wreg[j][2] = w0.z; wreg[j][3] = w0.w;
        wreg[j][4] = w1.x; wreg[j][5] = w1.y; wreg[j][6] = w1.z; wreg[j][7] = w1.w;
    }
    float qab = (lane < kH) ? g_qab[lane] : 0.f;
#pragma unroll 1
    for (int rr = 0; rr < 4; rr++) {
        int ur = warp * 4 + rr;
        int u  = u0 + ur;
        if (u >= kM1) continue;
        float vals[8];
        float s = 0.f, sq = 0.f;
#pragma unroll
        for (int j = 0; j < 8; j++) {
            float t = sx[ur][lane + 32 * j];
            vals[j] = t; s += t; sq += t * t;
        }
#pragma unroll
        for (int o = 16; o; o >>= 1) {
            s  += __shfl_xor_sync(0xffffffffu, s,  o);
            sq += __shfl_xor_sync(0xffffffffu, sq, o);
        }
        float mean = s * (1.f / kC);
        float var  = sq * (1.f / kC) - mean * mean;
        float rstd = rsqrtf(var + 1e-5f);
        float acc[8] = {};
#pragma unroll
        for (int j = 0; j < 8; j++) {
            int c = lane + 32 * j;
            float nv = (vals[j] - mean) * rstd * g[c] + b[c];
            g_nxh[(size_t)u * kC + c] = __float2bfloat16(nv);
            if (u < kU) __stcs(g_xr + (size_t)u * kC + c, vals[j]);
#pragma unroll
            for (int e = 0; e < 8; e++) acc[e] += nv * wreg[j][e];
        }
#pragma unroll
        for (int o = 16; o; o >>= 1)
#pragma unroll
            for (int e = 0; e < 8; e++)
                acc[e] += __shfl_xor_sync(0xffffffffu, acc[e], o);
        if (lane < kH) g_ql[(size_t)u * kH + lane] = (acc[lane] + qab) * kSCALE;
    }
}

// ============ bf16 GEMM (unchanged) ============
constexpr int HP   = 40;
constexpr int ASZH = 128 * HP;
constexpr int BSZH = 256 * HP;
constexpr int GEMM_SMEM = 3 * (ASZH + BSZH) * 2;
constexpr int BPITCH = 264;

__device__ __forceinline__ void mma_bf16(float (&d)[4], const uint32_t (&a)[4],
                                         const uint32_t (&bb)[2]) {
    asm volatile(
        "mma.sync.aligned.m16n8k16.row.col.f32.bf16.bf16.f32 "
        "{%0,%1,%2,%3}, {%4,%5,%6,%7}, {%8,%9}, {%0,%1,%2,%3};\n"
        : "+f"(d[0]), "+f"(d[1]), "+f"(d[2]), "+f"(d[3])
        : "r"(a[0]), "r"(a[1]), "r"(a[2]), "r"(a[3]), "r"(bb[0]), "r"(bb[1]));
}
__device__ __forceinline__ void cpa16(uint32_t dst, const void* src, bool pred) {
    int sz = pred ? 16 : 0;
    asm volatile("cp.async.cg.shared.global [%0], [%1], 16, %2;\n"
                 :: "r"(dst), "l"(src), "r"(sz));
}
__device__ __forceinline__ float gelu_exact(float x) {
    return 0.5f * x * (1.0f + erff(x * 0.70710678118654752f));
}

template<int EPI, int NPAIR>
__global__ void __launch_bounds__(512, 1) k_gemm7(const __nv_bfloat16* __restrict__ A1,
                                                  const __nv_bfloat16* __restrict__ W1,
                                                  const __nv_bfloat16* __restrict__ A2,
                                                  const __nv_bfloat16* __restrict__ W2,
                                                  const float* __restrict__ bias,
                                                  const float* __restrict__ addm,
                                                  float* __restrict__ D,
                                                  __nv_bfloat16* __restrict__ Dh,
                                                  const float* __restrict__ lng,
                                                  const float* __restrict__ lnb,
                                                  int M, int ldD) {
    extern __shared__ char smc[];
    __nv_bfloat16* As = (__nv_bfloat16*)smc;
    __nv_bfloat16* Bs = As + 3 * ASZH;
    float* ep = (float*)smc;
    uint32_t sA = (uint32_t)__cvta_generic_to_shared(As);
    uint32_t sB = (uint32_t)__cvta_generic_to_shared(Bs);

    int coly = blockIdx.y * 256;
    bias += coly;
    if (D)  D  += coly;
    if (Dh) Dh += coly;

    int tid = threadIdx.x, lane = tid & 31, warp = tid >> 5;
    int wm = warp >> 2, wn = warp & 3;
    int p = lane >> 2, q = lane & 3;
    int row0 = blockIdx.x * 128;
    int mbase = wm * 32, nbase = wn * 64;

    int ar = tid & 127, ah = tid >> 7;
    int bn = tid & 255, bh = tid >> 8;
    bool arow_ok = (row0 + ar) < M;
    const __nv_bfloat16* A1g = A1 + (size_t)(row0 + ar) * kC + ah * 8;
    const __nv_bfloat16* W1g = W1 + (size_t)(coly + bn) * kC + bh * 16;
    const __nv_bfloat16* A2g = (NPAIR == 2) ? (A2 + (size_t)(row0 + ar) * kC + ah * 8) : A1g;
    const __nv_bfloat16* W2g = (NPAIR == 2) ? (W2 + (size_t)(coly + bn) * kC + bh * 16) : W1g;
    uint32_t adst0 = sA + (uint32_t)((ar * HP + ah * 8) * 2);
    uint32_t bdst0 = sB + (uint32_t)((bn * HP + bh * 16) * 2);

    auto issue = [&](int kt) {
        int ktt = kt & 7;
        int buf = kt % 3;
        const __nv_bfloat16* as = ((NPAIR == 2 && (kt >> 3)) ? A2g : A1g) + ktt * 32;
        const __nv_bfloat16* bs = ((NPAIR == 2 && (kt >> 3)) ? W2g : W1g) + ktt * 32;
        cpa16(adst0 + (uint32_t)(buf * ASZH * 2), as, arow_ok);
        uint32_t bd = bdst0 + (uint32_t)(buf * BSZH * 2);
        cpa16(bd,      bs,     true);
        cpa16(bd + 16, bs + 8, true);
    };

    float acc[2][8][4] = {};
    const int TOT = 8 * NPAIR;

    issue(0);
    asm volatile("cp.async.commit_group;\n");
    issue(1);
    asm volatile("cp.async.commit_group;\n");

#pragma unroll 1
    for (int kt = 0; kt < TOT; kt++) {
        if (kt < TOT - 1) asm volatile("cp.async.wait_group 1;\n");
        else              asm volatile("cp.async.wait_group 0;\n");
        __syncthreads();
        if (kt + 2 < TOT) {
            issue(kt + 2);
            asm volatile("cp.async.commit_group;\n");
        }
        int buf = kt % 3;
        const __nv_bfloat16* Ab = As + buf * ASZH;
        const __nv_bfloat16* Bb = Bs + buf * BSZH;
#pragma unroll
        for (int kk = 0; kk < 32; kk += 16) {
            uint32_t af[2][4], bf[8][2];
#pragma unroll
            for (int mi = 0; mi < 2; mi++) {
                const __nv_bfloat16* a0 = Ab + (mbase + mi * 16 + p) * HP + kk + 2 * q;
                af[mi][0] = *(const uint32_t*)(a0);
                af[mi][1] = *(const uint32_t*)(a0 + 8 * HP);
                af[mi][2] = *(const uint32_t*)(a0 + 8);
                af[mi][3] = *(const uint32_t*)(a0 + 8 * HP + 8);
            }
#pragma unroll
            for (int ni = 0; ni < 8; ni++) {
                const __nv_bfloat16* b0 = Bb + (nbase + ni * 8 + p) * HP + kk + 2 * q;
                bf[ni][0] = *(const uint32_t*)(b0);
                bf[ni][1] = *(const uint32_t*)(b0 + 8);
            }
#pragma unroll
            for (int mi = 0; mi < 2; mi++)
#pragma unroll
                for (int ni = 0; ni < 8; ni++)
                    mma_bf16(acc[mi][ni], af[mi], bf[ni]);
        }
    }
    __syncthreads();

    if (EPI == 0 || EPI == 2) {
#pragma unroll
        for (int mi = 0; mi < 2; mi++) {
            int r1 = row0 + mbase + mi * 16 + p;
            int r2 = r1 + 8;
#pragma unroll
            for (int ni = 0; ni < 8; ni++) {
                int cc = nbase + ni * 8 + 2 * q;
                float2 bv = *(const float2*)(bias + cc);
                float d0 = acc[mi][ni][0] + bv.x, d1 = acc[mi][ni][1] + bv.y;
                float d2 = acc[mi][ni][2] + bv.x, d3 = acc[mi][ni][3] + bv.y;
                if (EPI == 2) {
                    d0 = gelu_exact(d0); d1 = gelu_exact(d1);
                    d2 = gelu_exact(d2); d3 = gelu_exact(d3);
                }
                __nv_bfloat162 o1 = {__float2bfloat16(d0), __float2bfloat16(d1)};
                __nv_bfloat162 o2 = {__float2bfloat16(d2), __float2bfloat16(d3)};
                if (r1 < M) *(__nv_bfloat162*)(Dh + (size_t)r1 * ldD + cc) = o1;
                if (r2 < M) *(__nv_bfloat162*)(Dh + (size_t)r2 * ldD + cc) = o2;
            }
        }
    } else {
#pragma unroll 1
        for (int half = 0; half < 2; half++) {
            __syncthreads();
            if ((wm >> 1) == half) {
#pragma unroll
                for (int mi = 0; mi < 2; mi++) {
                    int lr1 = mbase + mi * 16 + p;
                    int lr2 = lr1 + 8;
                    int r1 = row0 + lr1, r2 = row0 + lr2;
                    int e1 = lr1 - half * 64, e2 = lr2 - half * 64;
#pragma unroll
                    for (int ni = 0; ni < 8; ni++) {
                        int cc = nbase + ni * 8 + 2 * q;
                        float2 bv = *(const float2*)(bias + cc);
                        float2 a1 = *(const float2*)(addm + (size_t)r1 * kC + cc);
                        float2 a2 = *(const float2*)(addm + (size_t)r2 * kC + cc);
                        float2 o1 = {acc[mi][ni][0] + bv.x + a1.x, acc[mi][ni][1] + bv.y + a1.y};
                        float2 o2 = {acc[mi][ni][2] + bv.x + a2.x, acc[mi][ni][3] + bv.y + a2.y};
                        if (EPI == 3) {
                            *(float2*)(D + (size_t)r1 * ldD + cc) = o1;
                            *(float2*)(D + (size_t)r2 * ldD + cc) = o2;
                        }
                        *(float2*)(ep + e1 * BPITCH + cc) = o1;
                        *(float2*)(ep + e2 * BPITCH + cc) = o2;
                    }
                }
            }
            __syncthreads();
            if (EPI == 3) {
                float gg[8], bb[8];
#pragma unroll
                for (int j = 0; j < 8; j++) {
                    int c = lane + 32 * j;
                    gg[j] = lng[c]; bb[j] = lnb[c];
                }
#pragma unroll
                for (int rr = 0; rr < 4; rr++) {
                    int lr = warp * 4 + rr;
                    float vals[8]; float s = 0.f, sq = 0.f;
#pragma unroll
                    for (int j = 0; j < 8; j++) {
                        float t = ep[lr * BPITCH + lane + 32 * j];
                        vals[j] = t; s += t; sq += t * t;
                    }
#pragma unroll
                    for (int o = 16; o; o >>= 1) {
                        s  += __shfl_xor_sync(0xffffffffu, s,  o);
                        sq += __shfl_xor_sync(0xffffffffu, sq, o);
                    }
                    float mean = s * (1.f / kC);
                    float var  = sq * (1.f / kC) - mean * mean;
                    float rstd = rsqrtf(var + 1e-5f);
                    int gr = row0 + half * 64 + lr;
#pragma unroll
                    for (int j = 0; j < 8; j++) {
                        int c = lane + 32 * j;
                        Dh[(size_t)gr * kC + c] = __float2bfloat16((vals[j] - mean) * rstd * gg[j] + bb[j]);
                    }
                }
            } else {
#pragma unroll 1
                for (int it = 0; it < 32; it++) {
                    int j = it * 512 + tid;
                    int c = j >> 6, rr = j & 63;
                    unsigned R = (unsigned)(row0 + half * 64 + rr);
                    unsigned b = R / 25u;
                    unsigned v = R - b * 25u;
                    unsigned n = b >> 6, t = b & 63u;
                    D[(size_t)n * kXN + (size_t)c * kTV + t * kV + v] = ep[rr * BPITCH + c];
                }
            }
        }
    }
}

// ============ pool v7: v5 minus window means; writes pk (fp32) ============
constexpr int KAP = 12;
__global__ void __launch_bounds__(256, 3) k_pool(const float* __restrict__ ka_w,
                                                 const float* __restrict__ ka_b) {
    __shared__ int   su[2][kL];
    __shared__ float sqw[2][kH][128];
    __shared__ float skw[2][kH][128];
    __shared__ float spq[2][kC];
    __shared__ __align__(16) float skaw[kC * KAP];
    __shared__ float sred[2][4][kH][9];
    int tid = threadIdx.x, lane = tid & 31;
    int half = tid >> 7;
    int ti = tid & 127;
    int wh = ti >> 5;
    int b = (gridDim.x - 1 - blockIdx.x) * 2 + half;   // reversed: MRU-first
    int n = b / kT, t = b % kT;
    int hch = ti >> 4;

    for (int i = tid; i < kC * kH; i += 256) {
        int c = i >> 3, e = i & 7;
        skaw[c * KAP + e] = ka_w[i];
    }
    if (ti < kL) {
        int w = ti / kV, v = ti - w * kV;
        int tp = t + w - 2;
        su[half][ti] = (tp >= 0 && tp < kT) ? (n * kT + tp) * kV + v : kU;
    }
    float kab = (lane < kH) ? ka_b[lane] : 0.f;
    __syncthreads();

    // ---- q-weight softmax ----
#pragma unroll
    for (int hi = 0; hi < 2; hi++) {
        int hh = 2 * wh + hi;
        float lv[4]; float mx = -1e30f;
#pragma unroll
        for (int i = 0; i < 4; i++) {
            int l = lane + 32 * i;
            lv[i] = (l < kL) ? g_ql[(size_t)su[half][l] * kH + hh] : -1e30f;
            mx = fmaxf(mx, lv[i]);
        }
#pragma unroll
        for (int o = 16; o; o >>= 1) mx = fmaxf(mx, __shfl_xor_sync(0xffffffffu, mx, o));
        float sm = 0.f;
#pragma unroll
        for (int i = 0; i < 4; i++) {
            int l = lane + 32 * i;
            lv[i] = (l < kL) ? expf(lv[i] - mx) : 0.f;
            sm += lv[i];
        }
#pragma unroll
        for (int o = 16; o; o >>= 1) sm += __shfl_xor_sync(0xffffffffu, sm, o);
        float inv = 1.f / sm;
#pragma unroll
        for (int i = 0; i < 4; i++) {
            int l = lane + 32 * i;
            if (l < kL) sqw[half][hh][l] = lv[i] * inv;
        }
    }
    __syncthreads();

    // ---- pass A: pq only ----
    float pq0 = 0.f, pq1 = 0.f;
#pragma unroll 5
    for (int v = 0; v < kV; v++) {
#pragma unroll
        for (int w = 0; w < kWIN; w++) {
            int l = w * kV + v;
            float2 xv = bf2f(*(const uint32_t*)(g_qkvh + (size_t)su[half][l] * kC3 + 2 * ti));
            float sw = sqw[half][hch][l];
            pq0 += sw * xv.x; pq1 += sw * xv.y;
        }
    }
    spq[half][2 * ti]     = pq0;
    spq[half][2 * ti + 1] = pq1;
    __syncthreads();

    // ---- pass B: k logits ----
#pragma unroll 1
    for (int l = wh; l < kL; l += 4) {
        const __nv_bfloat16* kr = g_qkvh + (size_t)su[half][l] * kC3 + 256;
        float acc[8] = {};
#pragma unroll
        for (int j = 0; j < 4; j++) {
            int cp = lane + 32 * j;
            int c0 = 2 * cp;
            __nv_bfloat162 kv = *(const __nv_bfloat162*)(kr + c0);
            float2 pq2 = *(const float2*)(spq[half] + c0);
            float kp0 = __bfloat162float(kv.x) * pq2.x;
            float kp1 = __bfloat162float(kv.y) * pq2.y;
            const float4* ka0 = (const float4*)(skaw + c0 * KAP);
            const float4* ka1 = (const float4*)(skaw + (c0 + 1) * KAP);
            float4 a0 = ka0[0], a1 = ka0[1], b0 = ka1[0], b1 = ka1[1];
            acc[0] += kp0 * a0.x + kp1 * b0.x; acc[1] += kp0 * a0.y + kp1 * b0.y;
            acc[2] += kp0 * a0.z + kp1 * b0.z; acc[3] += kp0 * a0.w + kp1 * b0.w;
            acc[4] += kp0 * a1.x + kp1 * b1.x; acc[5] += kp0 * a1.y + kp1 * b1.y;
            acc[6] += kp0 * a1.z + kp1 * b1.z; acc[7] += kp0 * a1.w + kp1 * b1.w;
        }
#pragma unroll
        for (int o = 16; o >= 8; o >>= 1)
#pragma unroll
            for (int e = 0; e < 8; e++)
                acc[e] += __shfl_xor_sync(0xffffffffu, acc[e], o);
        if (lane < 8) {
#pragma unroll
            for (int e = 0; e < 8; e++) sred[half][wh][lane][e] = acc[e];
        }
        __syncwarp();
        if (lane < 8) {
            float s2 = 0.f;
#pragma unroll
            for (int m = 0; m < 8; m++) s2 += sred[half][wh][m][lane];
            skw[half][lane][l] = (s2 + kab) * kSCALE;
        }
        __syncwarp();
    }
    __syncthreads();

    // ---- k-weight softmax ----
#pragma unroll
    for (int hi = 0; hi < 2; hi++) {
        int hh = 2 * wh + hi;
        float lv[4]; float mx = -1e30f;
#pragma unroll
        for (int i = 0; i < 4; i++) {
            int l = lane + 32 * i;
            lv[i] = (l < kL) ? skw[half][hh][l] : -1e30f;
            mx = fmaxf(mx, lv[i]);
        }
#pragma unroll
        for (int o = 16; o; o >>= 1) mx = fmaxf(mx, __shfl_xor_sync(0xffffffffu, mx, o));
        float sm = 0.f;
#pragma unroll
        for (int i = 0; i < 4; i++) {
            int l = lane + 32 * i;
            lv[i] = (l < kL) ? expf(lv[i] - mx) : 0.f;
            sm += lv[i];
        }
#pragma unroll
        for (int o = 16; o; o >>= 1) sm += __shfl_xor_sync(0xffffffffu, sm, o);
        float inv = 1.f / sm;
#pragma unroll
        for (int i = 0; i < 4; i++) {
            int l = lane + 32 * i;
            if (l < kL) skw[half][hh][l] = lv[i] * inv;
        }
    }
    __syncthreads();

    // ---- pass C1: pk -> g_pk ----
    float pk0 = 0.f, pk1 = 0.f;
#pragma unroll 5
    for (int v = 0; v < kV; v++) {
#pragma unroll
        for (int w = 0; w < kWIN; w++) {
            int l = w * kV + v;
            float2 kv = bf2f(*(const uint32_t*)(g_qkvh + (size_t)su[half][l] * kC3 + 256 + 2 * ti));
            float sw = skw[half][hch][l];
            pk0 += sw * kv.x;
            pk1 += sw * kv.y;
        }
    }
    float2 pko = {pk0, pk1};
    *(float2*)(g_pk + (size_t)b * kC + 2 * ti) = pko;
}

// ============ slide: sliding window means -> mq, mkv = pk * mv ============
__global__ void __launch_bounds__(256) k_slide() {
    int gid = blockIdx.x * 256 + threadIdx.x;     // 102400
    int cp = gid & 127;                            // channel pair
    int j  = gid >> 7;                             // 0..799
    int n = j / kV, v = j - (j / kV) * kV;
    const __nv_bfloat16* qbase = g_qkvh + 2 * cp;
    const __nv_bfloat16* vbase = g_qkvh + 512 + 2 * cp;

    // ring[i] = token t-2+i ; pre-loop holds tp = -2..1
    float2 q0 = {0.f, 0.f}, q1 = {0.f, 0.f}, q2, q3;
    float2 v0 = {0.f, 0.f}, v1 = {0.f, 0.f}, v2, v3;
    {
        size_t u0 = (size_t)(n * kT + 0) * kV + v;
        size_t u1 = (size_t)(n * kT + 1) * kV + v;
        q2 = bf2f(*(const uint32_t*)(qbase + u0 * kC3));
        q3 = bf2f(*(const uint32_t*)(qbase + u1 * kC3));
        v2 = bf2f(*(const uint32_t*)(vbase + u0 * kC3));
        v3 = bf2f(*(const uint32_t*)(vbase + u1 * kC3));
    }
#pragma unroll 4
    for (int t = 0; t < kT; t++) {
        float2 q4 = {0.f, 0.f}, v4 = {0.f, 0.f};
        int tp = t + 2;
        if (tp < kT) {
            size_t u = (size_t)(n * kT + tp) * kV + v;
            q4 = bf2f(*(const uint32_t*)(qbase + u * kC3));
            v4 = bf2f(*(const uint32_t*)(vbase + u * kC3));
        }
        float qs0 = q0.x + q1.x + q2.x + q3.x + q4.x;
        float qs1 = q0.y + q1.y + q2.y + q3.y + q4.y;
        float vs0 = v0.x + v1.x + v2.x + v3.x + v4.x;
        float vs1 = v0.y + v1.y + v2.y + v3.y + v4.y;
        int b = n * kT + t;
        float2 pk2 = *(const float2*)(g_pk + (size_t)b * kC + 2 * cp);
        size_t o = ((size_t)b * kV + v) * kC + 2 * cp;
        stcs_u32(g_mqh  + o, f2bf2(qs0 * 0.2f, qs1 * 0.2f));
        stcs_u32(g_mkvh + o, f2bf2(pk2.x * vs0 * 0.2f, pk2.y * vs1 * 0.2f));
        q0 = q1; q1 = q2; q2 = q3; q3 = q4;
        v0 = v1; v1 = v2; v2 = v3; v3 = v4;
    }
}

// ===================================================================================
extern "C" void kernel_launch(void* const* d_in, const int* in_sizes, int n_in,
                              void* d_out, int out_size) {
    const float* x    = (const float*)d_in[0];
    const float* ln1g = (const float*)d_in[1];
    const float* ln1b = (const float*)d_in[2];
    const float* q_w  = (const float*)d_in[3];
    const float* q_b  = (const float*)d_in[4];
    const float* qa_w = (const float*)d_in[5];
    const float* qa_b = (const float*)d_in[6];
    const float* k_w  = (const float*)d_in[7];
    const float* k_b  = (const float*)d_in[8];
    const float* ka_w = (const float*)d_in[9];
    const float* ka_b = (const float*)d_in[10];
    const float* v_w  = (const float*)d_in[11];
    const float* v_b  = (const float*)d_in[12];
    const float* t_w  = (const float*)d_in[13];
    const float* t_b  = (const float*)d_in[14];
    const float* p_w  = (const float*)d_in[15];
    const float* p_b  = (const float*)d_in[16];
    const float* ffng = (const float*)d_in[17];
    const float* ffnb = (const float*)d_in[18];
    const float* w1   = (const float*)d_in[19];
    const float* b1   = (const float*)d_in[20];
    const float* w2   = (const float*)d_in[21];
    const float* b2   = (const float*)d_in[22];
    float* out = (float*)d_out;

    float *p_k, *p_xr, *p_tb, *p_qkvb;
    __nv_bfloat16 *p_nxh, *p_qkvh, *p_fh, *p_mkvh, *p_mqh, *p_h1h, *p_twT, *p_wqkvT, *p_wpT, *p_w1T, *p_w2T;
    cudaGetSymbolAddress((void**)&p_k,     g_k);
    cudaGetSymbolAddress((void**)&p_xr,    g_xr);
    cudaGetSymbolAddress((void**)&p_tb,    g_tb);
    cudaGetSymbolAddress((void**)&p_qkvb,  g_qkvb);
    cudaGetSymbolAddress((void**)&p_nxh,   g_nxh);
    cudaGetSymbolAddress((void**)&p_qkvh,  g_qkvh);
    cudaGetSymbolAddress((void**)&p_fh,    g_fh);
    cudaGetSymbolAddress((void**)&p_mkvh,  g_mkvh);
    cudaGetSymbolAddress((void**)&p_mqh,   g_mqh);
    cudaGetSymbolAddress((void**)&p_h1h,   g_h1h);
    cudaGetSymbolAddress((void**)&p_twT,   g_twT);
    cudaGetSymbolAddress((void**)&p_wqkvT, g_wqkvT);
    cudaGetSymbolAddress((void**)&p_wpT,   g_wpT);
    cudaGetSymbolAddress((void**)&p_w1T,   g_w1T);
    cudaGetSymbolAddress((void**)&p_w2T,   g_w2T);

    cudaFuncSetAttribute(k_gemm7<0,1>, cudaFuncAttributeMaxDynamicSharedMemorySize, GEMM_SMEM);
    cudaFuncSetAttribute(k_gemm7<2,1>, cudaFuncAttributeMaxDynamicSharedMemorySize, GEMM_SMEM);
    cudaFuncSetAttribute(k_gemm7<3,2>, cudaFuncAttributeMaxDynamicSharedMemorySize, GEMM_SMEM);
    cudaFuncSetAttribute(k_gemm7<4,1>, cudaFuncAttributeMaxDynamicSharedMemorySize, GEMM_SMEM);

    dim3 gqkv((kM1 + 127) / 128, 3);   // 401 x 3
    int g2 = kU / 128;                 // 400

    // 0) prep
    k_prep<<<257 + 384 + 3 + 1, 256>>>(t_w, p_w, t_b, p_b, q_w, k_w, v_w, w1, w2,
                                       q_b, k_b, v_b, qa_w, qa_b);
    // 1) LN -> bf16 nx + fp32 xr + fused qlog
    k_ln_x<<<(kM1 + 31) / 32, 256>>>(x, ln1g, ln1b);
    // 2) fused q|k|v projection -> g_qkvh bf16
    k_gemm7<0,1><<<gqkv, 512, GEMM_SMEM>>>(p_nxh, p_wqkvT, nullptr, nullptr, p_qkvb, nullptr,
                                           nullptr, p_qkvh, nullptr, nullptr, kM1, kC3);
    // 3) pooling v7: pq, kw, pk only
    k_pool<<<kB / 2, 256>>>(ka_w, ka_b);
    // 4) sliding means: mq, mkv = pk * mv
    k_slide<<<400, 256>>>();
    // 5) attraw = mkv@tp_w + mq@p_w + tp_b + xr -> g_k ; fused LN -> f bf16
    k_gemm7<3,2><<<g2, 512, GEMM_SMEM>>>(p_mkvh, p_twT, p_mqh, p_wpT, p_tb, p_xr,
                                         p_k, p_fh, ffng, ffnb, kU, kC);
    // 6) h1 = gelu(f @ w1 + b1) -> bf16
    k_gemm7<2,1><<<g2, 512, GEMM_SMEM>>>(p_fh, p_w1T, nullptr, nullptr, b1, nullptr,
                                         nullptr, p_h1h, nullptr, nullptr, kU, kC);
    // 7) y = h1 @ w2 + b2 + attraw -> transposed out
    k_gemm7<4,1><<<g2, 512, GEMM_SMEM>>>(p_h1h, p_w2T, nullptr, nullptr, b2, p_k,
                                         out, nullptr, nullptr, nullptr, kU, kC);
}

// round 16
// speedup vs baseline: 1.0414x; 1.0199x over previous
#include <cuda_runtime.h>
#include <cuda_bf16.h>
#include <cstdint>
#include <cstddef>

constexpr int kN   = 32;
constexpr int kC   = 256;
constexpr int kC3  = 768;
constexpr int kT   = 64;
constexpr int kV   = 25;
constexpr int kH   = 8;
constexpr int kWIN = 5;
constexpr int kB   = kN * kT;        // 2048 windows
constexpr int kL   = kWIN * kV;      // 125
constexpr int kU   = kB * kV;        // 51200 unique tokens
constexpr int kM1  = kU + 1;         // + pad row
constexpr int kTV  = kT * kV;        // 1600
constexpr int kXN  = kC * kTV;       // 409600
constexpr float kSCALE = 0.17677669529663687f;  // 1/sqrt(32)

// ---------------- scratch ----------------
__device__ __nv_bfloat16 g_nxh [(size_t)kM1 * kC];
__device__ __nv_bfloat16 g_qkvh[(size_t)kM1 * kC3];
__device__ float         g_k   [(size_t)kM1 * kC];
__device__ __nv_bfloat16 g_fh  [(size_t)kU  * kC];
__device__ float         g_xr  [(size_t)kU  * kC];
__device__ __nv_bfloat16 g_mkvh[(size_t)kU  * kC];
__device__ __nv_bfloat16 g_mqh [(size_t)kU  * kC];
__device__ __nv_bfloat16 g_h1h [(size_t)kU  * kC];
__device__ float         g_ql  [(size_t)kM1 * kH];
__device__ __nv_bfloat16 g_twT [65536];
__device__ float         g_tb  [kC];
__device__ __nv_bfloat16 g_wqkvT[(size_t)kC3 * kC];
__device__ __nv_bfloat16 g_wpT [65536];
__device__ __nv_bfloat16 g_w1T [65536];
__device__ __nv_bfloat16 g_w2T [65536];
__device__ float         g_qkvb[kC3];
__device__ float         g_qaw [kC * kH];
__device__ float         g_qab [kH];

__device__ __forceinline__ void stcs_u32(void* p, uint32_t v) {
    asm volatile("st.global.cs.b32 [%0], %1;" :: "l"(p), "r"(v));
}
__device__ __forceinline__ float2 bf2f(uint32_t u) {
    __nv_bfloat162 h = *(__nv_bfloat162*)&u;
    return make_float2(__bfloat162float(h.x), __bfloat162float(h.y));
}
__device__ __forceinline__ uint32_t f2bf2(float a, float b) {
    __nv_bfloat162 h = {__float2bfloat16(a), __float2bfloat16(b)};
    return *(uint32_t*)&h;
}

// ============ prep ============
__global__ void __launch_bounds__(256) k_prep(const float* __restrict__ t_w,
                                              const float* __restrict__ p_w,
                                              const float* __restrict__ t_b,
                                              const float* __restrict__ p_b,
                                              const float* __restrict__ q_w,
                                              const float* __restrict__ k_w,
                                              const float* __restrict__ v_w,
                                              const float* __restrict__ w1,
                                              const float* __restrict__ w2,
                                              const float* __restrict__ q_b,
                                              const float* __restrict__ k_b,
                                              const float* __restrict__ v_b,
                                              const float* __restrict__ qa_w,
                                              const float* __restrict__ qa_b) {
    int bid = blockIdx.x, tid = threadIdx.x;
    if (bid < 257) {
        __shared__ float srow[kC];
        bool isw = (bid < kC);
        srow[tid] = isw ? t_w[(size_t)bid * kC + tid] : t_b[tid];
        __syncthreads();
        float acc = isw ? 0.f : p_b[tid];
#pragma unroll 8
        for (int m = 0; m < kC; m++) acc += srow[m] * p_w[(size_t)m * kC + tid];
        if (isw) g_twT[(size_t)tid * kC + bid] = __float2bfloat16(acc);
        else     g_tb[tid] = acc;
    } else if (bid < 257 + 384) {
        __shared__ float tile[32][33];
        int t = bid - 257;
        int w = t >> 6; t &= 63;
        int k0 = (t >> 3) * 32, n0 = (t & 7) * 32;
        const float* s = (w == 0) ? q_w : (w == 1) ? k_w : (w == 2) ? v_w
                       : (w == 3) ? p_w : (w == 4) ? w1 : w2;
        __nv_bfloat16* dT = (w < 3) ? (g_wqkvT + (size_t)w * 256 * kC)
                          : (w == 3) ? g_wpT : (w == 4) ? g_w1T : g_w2T;
        int tx = tid & 31, ty = tid >> 5;
#pragma unroll
        for (int j = 0; j < 4; j++)
            tile[ty + 8 * j][tx] = s[(size_t)(k0 + ty + 8 * j) * kC + n0 + tx];
        __syncthreads();
#pragma unroll
        for (int j = 0; j < 4; j++)
            dT[(size_t)(n0 + ty + 8 * j) * kC + k0 + tx] = __float2bfloat16(tile[tx][ty + 8 * j]);
    } else if (bid < 257 + 384 + 3) {
        int k = bid - (257 + 384);
        g_qkvb[k * 256 + tid] = (k == 0) ? q_b[tid] : (k == 1) ? k_b[tid] : v_b[tid];
    } else {
        __shared__ float sqa[kC][kH];
        for (int i = tid; i < kC * kH; i += 256) sqa[i >> 3][i & 7] = qa_w[i];
        __syncthreads();
        int c = tid;
        float acc[8] = {};
        const float* qr = q_w + (size_t)c * kC;
#pragma unroll 4
        for (int j = 0; j < kC; j++) {
            float qv = qr[j];
#pragma unroll
            for (int e = 0; e < 8; e++) acc[e] += qv * sqa[j][e];
        }
#pragma unroll
        for (int e = 0; e < 8; e++) g_qaw[c * kH + e] = acc[e];
        if (tid < kH) {
            float a = qa_b[tid];
            for (int j = 0; j < kC; j++) a += q_b[j] * sqa[j][tid];
            g_qab[tid] = a;
        }
    }
}

// ============ LN of unique tokens -> bf16 nx, raw xr (.cs), fused qlog ============
__global__ void __launch_bounds__(256) k_ln_x(const float* __restrict__ x,
                                              const float* __restrict__ g,
                                              const float* __restrict__ b) {
    __shared__ float sx[32][257];
    int tid = threadIdx.x;
    int u0  = blockIdx.x * 32;
    {
        int ur = tid & 31;
        int u  = u0 + ur;
        int cb = tid >> 5;
        bool has = (u < kU);
        size_t base = 0;
        if (has) { int n = u / kTV; base = (size_t)n * kXN + (u - n * kTV); }
#pragma unroll
        for (int j = 0; j < 32; j++) {
            int c = cb * 32 + j;
            sx[ur][c] = has ? x[base + (size_t)c * kTV] : 0.f;
        }
    }
    __syncthreads();
    int lane = tid & 31, warp = tid >> 5;
    float wreg[8][8];
#pragma unroll
    for (int j = 0; j < 8; j++) {
        const float4* wr = (const float4*)(g_qaw + (size_t)(lane + 32 * j) * kH);
        float4 w0 = wr[0], w1 = wr[1];
        wreg[j][0] = w0.x; wreg[j][1] = w0.y; wreg[j][2] = w0.z; wreg[j][3] = w0.w;
        wreg[j][4] = w1.x; wreg[j][5] = w1.y; wreg[j][6] = w1.z; wreg[j][7] = w1.w;
    }
    float qab = (lane < kH) ? g_qab[lane] : 0.f;
#pragma unroll 1
    for (int rr = 0; rr < 4; rr++) {
        int ur = warp * 4 + rr;
        int u  = u0 + ur;
        if (u >= kM1) continue;
        float vals[8];
        float s = 0.f, sq = 0.f;
#pragma unroll
        for (int j = 0; j < 8; j++) {
            float t = sx[ur][lane + 32 * j];
            vals[j] = t; s += t; sq += t * t;
        }
#pragma unroll
        for (int o = 16; o; o >>= 1) {
            s  += __shfl_xor_sync(0xffffffffu, s,  o);
            sq += __shfl_xor_sync(0xffffffffu, sq, o);
        }
        float mean = s * (1.f / kC);
        float var  = sq * (1.f / kC) - mean * mean;
        float rstd = rsqrtf(var + 1e-5f);
        float acc[8] = {};
#pragma unroll
        for (int j = 0; j < 8; j++) {
            int c = lane + 32 * j;
            float nv = (vals[j] - mean) * rstd * g[c] + b[c];
            g_nxh[(size_t)u * kC + c] = __float2bfloat16(nv);
            if (u < kU) __stcs(g_xr + (size_t)u * kC + c, vals[j]);
#pragma unroll
            for (int e = 0; e < 8; e++) acc[e] += nv * wreg[j][e];
        }
#pragma unroll
        for (int o = 16; o; o >>= 1)
#pragma unroll
            for (int e = 0; e < 8; e++)
                acc[e] += __shfl_xor_sync(0xffffffffu, acc[e], o);
        if (lane < kH) g_ql[(size_t)u * kH + lane] = (acc[lane] + qab) * kSCALE;
    }
}

// ============ bf16 GEMM (unchanged) ============
constexpr int HP   = 40;
constexpr int ASZH = 128 * HP;
constexpr int BSZH = 256 * HP;
constexpr int GEMM_SMEM = 3 * (ASZH + BSZH) * 2;
constexpr int BPITCH = 264;

__device__ __forceinline__ void mma_bf16(float (&d)[4], const uint32_t (&a)[4],
                                         const uint32_t (&bb)[2]) {
    asm volatile(
        "mma.sync.aligned.m16n8k16.row.col.f32.bf16.bf16.f32 "
        "{%0,%1,%2,%3}, {%4,%5,%6,%7}, {%8,%9}, {%0,%1,%2,%3};\n"
        : "+f"(d[0]), "+f"(d[1]), "+f"(d[2]), "+f"(d[3])
        : "r"(a[0]), "r"(a[1]), "r"(a[2]), "r"(a[3]), "r"(bb[0]), "r"(bb[1]));
}
__device__ __forceinline__ void cpa16(uint32_t dst, const void* src, bool pred) {
    int sz = pred ? 16 : 0;
    asm volatile("cp.async.cg.shared.global [%0], [%1], 16, %2;\n"
                 :: "r"(dst), "l"(src), "r"(sz));
}
__device__ __forceinline__ float gelu_exact(float x) {
    return 0.5f * x * (1.0f + erff(x * 0.70710678118654752f));
}

template<int EPI, int NPAIR>
__global__ void __launch_bounds__(512, 1) k_gemm7(const __nv_bfloat16* __restrict__ A1,
                                                  const __nv_bfloat16* __restrict__ W1,
                                                  const __nv_bfloat16* __restrict__ A2,
                                                  const __nv_bfloat16* __restrict__ W2,
                                                  const float* __restrict__ bias,
                                                  const float* __restrict__ addm,
                                                  float* __restrict__ D,
                                                  __nv_bfloat16* __restrict__ Dh,
                                                  const float* __restrict__ lng,
                                                  const float* __restrict__ lnb,
                                                  int M, int ldD) {
    extern __shared__ char smc[];
    __nv_bfloat16* As = (__nv_bfloat16*)smc;
    __nv_bfloat16* Bs = As + 3 * ASZH;
    float* ep = (float*)smc;
    uint32_t sA = (uint32_t)__cvta_generic_to_shared(As);
    uint32_t sB = (uint32_t)__cvta_generic_to_shared(Bs);

    int coly = blockIdx.y * 256;
    bias += coly;
    if (D)  D  += coly;
    if (Dh) Dh += coly;

    int tid = threadIdx.x, lane = tid & 31, warp = tid >> 5;
    int wm = warp >> 2, wn = warp & 3;
    int p = lane >> 2, q = lane & 3;
    int row0 = blockIdx.x * 128;
    int mbase = wm * 32, nbase = wn * 64;

    int ar = tid & 127, ah = tid >> 7;
    int bn = tid & 255, bh = tid >> 8;
    bool arow_ok = (row0 + ar) < M;
    const __nv_bfloat16* A1g = A1 + (size_t)(row0 + ar) * kC + ah * 8;
    const __nv_bfloat16* W1g = W1 + (size_t)(coly + bn) * kC + bh * 16;
    const __nv_bfloat16* A2g = (NPAIR == 2) ? (A2 + (size_t)(row0 + ar) * kC + ah * 8) : A1g;
    const __nv_bfloat16* W2g = (NPAIR == 2) ? (W2 + (size_t)(coly + bn) * kC + bh * 16) : W1g;
    uint32_t adst0 = sA + (uint32_t)((ar * HP + ah * 8) * 2);
    uint32_t bdst0 = sB + (uint32_t)((bn * HP + bh * 16) * 2);

    auto issue = [&](int kt) {
        int ktt = kt & 7;
        int buf = kt % 3;
        const __nv_bfloat16* as = ((NPAIR == 2 && (kt >> 3)) ? A2g : A1g) + ktt * 32;
        const __nv_bfloat16* bs = ((NPAIR == 2 && (kt >> 3)) ? W2g : W1g) + ktt * 32;
        cpa16(adst0 + (uint32_t)(buf * ASZH * 2), as, arow_ok);
        uint32_t bd = bdst0 + (uint32_t)(buf * BSZH * 2);
        cpa16(bd,      bs,     true);
        cpa16(bd + 16, bs + 8, true);
    };

    float acc[2][8][4] = {};
    const int TOT = 8 * NPAIR;

    issue(0);
    asm volatile("cp.async.commit_group;\n");
    issue(1);
    asm volatile("cp.async.commit_group;\n");

#pragma unroll 1
    for (int kt = 0; kt < TOT; kt++) {
        if (kt < TOT - 1) asm volatile("cp.async.wait_group 1;\n");
        else              asm volatile("cp.async.wait_group 0;\n");
        __syncthreads();
        if (kt + 2 < TOT) {
            issue(kt + 2);
            asm volatile("cp.async.commit_group;\n");
        }
        int buf = kt % 3;
        const __nv_bfloat16* Ab = As + buf * ASZH;
        const __nv_bfloat16* Bb = Bs + buf * BSZH;
#pragma unroll
        for (int kk = 0; kk < 32; kk += 16) {
            uint32_t af[2][4], bf[8][2];
#pragma unroll
            for (int mi = 0; mi < 2; mi++) {
                const __nv_bfloat16* a0 = Ab + (mbase + mi * 16 + p) * HP + kk + 2 * q;
                af[mi][0] = *(const uint32_t*)(a0);
                af[mi][1] = *(const uint32_t*)(a0 + 8 * HP);
                af[mi][2] = *(const uint32_t*)(a0 + 8);
                af[mi][3] = *(const uint32_t*)(a0 + 8 * HP + 8);
            }
#pragma unroll
            for (int ni = 0; ni < 8; ni++) {
                const __nv_bfloat16* b0 = Bb + (nbase + ni * 8 + p) * HP + kk + 2 * q;
                bf[ni][0] = *(const uint32_t*)(b0);
                bf[ni][1] = *(const uint32_t*)(b0 + 8);
            }
#pragma unroll
            for (int mi = 0; mi < 2; mi++)
#pragma unroll
                for (int ni = 0; ni < 8; ni++)
                    mma_bf16(acc[mi][ni], af[mi], bf[ni]);
        }
    }
    __syncthreads();

    if (EPI == 0 || EPI == 2) {
#pragma unroll
        for (int mi = 0; mi < 2; mi++) {
            int r1 = row0 + mbase + mi * 16 + p;
            int r2 = r1 + 8;
#pragma unroll
            for (int ni = 0; ni < 8; ni++) {
                int cc = nbase + ni * 8 + 2 * q;
                float2 bv = *(const float2*)(bias + cc);
                float d0 = acc[mi][ni][0] + bv.x, d1 = acc[mi][ni][1] + bv.y;
                float d2 = acc[mi][ni][2] + bv.x, d3 = acc[mi][ni][3] + bv.y;
                if (EPI == 2) {
                    d0 = gelu_exact(d0); d1 = gelu_exact(d1);
                    d2 = gelu_exact(d2); d3 = gelu_exact(d3);
                }
                __nv_bfloat162 o1 = {__float2bfloat16(d0), __float2bfloat16(d1)};
                __nv_bfloat162 o2 = {__float2bfloat16(d2), __float2bfloat16(d3)};
                if (r1 < M) *(__nv_bfloat162*)(Dh + (size_t)r1 * ldD + cc) = o1;
                if (r2 < M) *(__nv_bfloat162*)(Dh + (size_t)r2 * ldD + cc) = o2;
            }
        }
    } else {
#pragma unroll 1
        for (int half = 0; half < 2; half++) {
            __syncthreads();
            if ((wm >> 1) == half) {
#pragma unroll
                for (int mi = 0; mi < 2; mi++) {
                    int lr1 = mbase + mi * 16 + p;
                    int lr2 = lr1 + 8;
                    int r1 = row0 + lr1, r2 = row0 + lr2;
                    int e1 = lr1 - half * 64, e2 = lr2 - half * 64;
#pragma unroll
                    for (int ni = 0; ni < 8; ni++) {
                        int cc = nbase + ni * 8 + 2 * q;
                        float2 bv = *(const float2*)(bias + cc);
                        float2 a1 = *(const float2*)(addm + (size_t)r1 * kC + cc);
                        float2 a2 = *(const float2*)(addm + (size_t)r2 * kC + cc);
                        float2 o1 = {acc[mi][ni][0] + bv.x + a1.x, acc[mi][ni][1] + bv.y + a1.y};
                        float2 o2 = {acc[mi][ni][2] + bv.x + a2.x, acc[mi][ni][3] + bv.y + a2.y};
                        if (EPI == 3) {
                            *(float2*)(D + (size_t)r1 * ldD + cc) = o1;
                            *(float2*)(D + (size_t)r2 * ldD + cc) = o2;
                        }
                        *(float2*)(ep + e1 * BPITCH + cc) = o1;
                        *(float2*)(ep + e2 * BPITCH + cc) = o2;
                    }
                }
            }
            __syncthreads();
            if (EPI == 3) {
                float gg[8], bb[8];
#pragma unroll
                for (int j = 0; j < 8; j++) {
                    int c = lane + 32 * j;
                    gg[j] = lng[c]; bb[j] = lnb[c];
                }
#pragma unroll
                for (int rr = 0; rr < 4; rr++) {
                    int lr = warp * 4 + rr;
                    float vals[8]; float s = 0.f, sq = 0.f;
#pragma unroll
                    for (int j = 0; j < 8; j++) {
                        float t = ep[lr * BPITCH + lane + 32 * j];
                        vals[j] = t; s += t; sq += t * t;
                    }
#pragma unroll
                    for (int o = 16; o; o >>= 1) {
                        s  += __shfl_xor_sync(0xffffffffu, s,  o);
                        sq += __shfl_xor_sync(0xffffffffu, sq, o);
                    }
                    float mean = s * (1.f / kC);
                    float var  = sq * (1.f / kC) - mean * mean;
                    float rstd = rsqrtf(var + 1e-5f);
                    int gr = row0 + half * 64 + lr;
#pragma unroll
                    for (int j = 0; j < 8; j++) {
                        int c = lane + 32 * j;
                        Dh[(size_t)gr * kC + c] = __float2bfloat16((vals[j] - mean) * rstd * gg[j] + bb[j]);
                    }
                }
            } else {
#pragma unroll 1
                for (int it = 0; it < 32; it++) {
                    int j = it * 512 + tid;
                    int c = j >> 6, rr = j & 63;
                    unsigned R = (unsigned)(row0 + half * 64 + rr);
                    unsigned b = R / 25u;
                    unsigned v = R - b * 25u;
                    unsigned n = b >> 6, t = b & 63u;
                    D[(size_t)n * kXN + (size_t)c * kTV + t * kV + v] = ep[rr * BPITCH + c];
                }
            }
        }
    }
}

// ============ pool v5 @ 4 CTA/SM: 2 windows/CTA, bf16x2 pairs, inline means ============
constexpr int KAP = 12;
__global__ void __launch_bounds__(256, 4) k_pool(const float* __restrict__ ka_w,
                                                 const float* __restrict__ ka_b) {
    __shared__ int   su[2][kL];
    __shared__ float sqw[2][kH][128];
    __shared__ float skw[2][kH][128];
    __shared__ float spq[2][kC];
    __shared__ __align__(16) float skaw[kC * KAP];
    __shared__ float sred[2][4][kH][9];
    int tid = threadIdx.x, lane = tid & 31;
    int half = tid >> 7;
    int ti = tid & 127;
    int wh = ti >> 5;
    int b = (gridDim.x - 1 - blockIdx.x) * 2 + half;   // reversed: MRU-first
    int n = b / kT, t = b % kT;
    int hch = ti >> 4;

    for (int i = tid; i < kC * kH; i += 256) {
        int c = i >> 3, e = i & 7;
        skaw[c * KAP + e] = ka_w[i];
    }
    if (ti < kL) {
        int w = ti / kV, v = ti - w * kV;
        int tp = t + w - 2;
        su[half][ti] = (tp >= 0 && tp < kT) ? (n * kT + tp) * kV + v : kU;
    }
    float kab = (lane < kH) ? ka_b[lane] : 0.f;
    __syncthreads();

    // ---- q-weight softmax: warp wh handles heads 2wh, 2wh+1 ----
#pragma unroll
    for (int hi = 0; hi < 2; hi++) {
        int hh = 2 * wh + hi;
        float lv[4]; float mx = -1e30f;
#pragma unroll
        for (int i = 0; i < 4; i++) {
            int l = lane + 32 * i;
            lv[i] = (l < kL) ? g_ql[(size_t)su[half][l] * kH + hh] : -1e30f;
            mx = fmaxf(mx, lv[i]);
        }
#pragma unroll
        for (int o = 16; o; o >>= 1) mx = fmaxf(mx, __shfl_xor_sync(0xffffffffu, mx, o));
        float sm = 0.f;
#pragma unroll
        for (int i = 0; i < 4; i++) {
            int l = lane + 32 * i;
            lv[i] = (l < kL) ? expf(lv[i] - mx) : 0.f;
            sm += lv[i];
        }
#pragma unroll
        for (int o = 16; o; o >>= 1) sm += __shfl_xor_sync(0xffffffffu, sm, o);
        float inv = 1.f / sm;
#pragma unroll
        for (int i = 0; i < 4; i++) {
            int l = lane + 32 * i;
            if (l < kL) sqw[half][hh][l] = lv[i] * inv;
        }
    }
    __syncthreads();

    // ---- pass A: pq + mq ----
    float pq0 = 0.f, pq1 = 0.f;
#pragma unroll 5
    for (int v = 0; v < kV; v++) {
        float a0 = 0.f, a1 = 0.f;
#pragma unroll
        for (int w = 0; w < kWIN; w++) {
            int l = w * kV + v;
            float2 xv = bf2f(*(const uint32_t*)(g_qkvh + (size_t)su[half][l] * kC3 + 2 * ti));
            float sw = sqw[half][hch][l];
            pq0 += sw * xv.x; pq1 += sw * xv.y;
            a0 += xv.x; a1 += xv.y;
        }
        stcs_u32(g_mqh + ((size_t)b * kV + v) * kC + 2 * ti, f2bf2(a0 * 0.2f, a1 * 0.2f));
    }
    spq[half][2 * ti]     = pq0;
    spq[half][2 * ti + 1] = pq1;
    __syncthreads();

    // ---- pass B: k logits ----
#pragma unroll 1
    for (int l = wh; l < kL; l += 4) {
        const __nv_bfloat16* kr = g_qkvh + (size_t)su[half][l] * kC3 + 256;
        float acc[8] = {};
#pragma unroll
        for (int j = 0; j < 4; j++) {
            int cp = lane + 32 * j;
            int c0 = 2 * cp;
            __nv_bfloat162 kv = *(const __nv_bfloat162*)(kr + c0);
            float2 pq2 = *(const float2*)(spq[half] + c0);
            float kp0 = __bfloat162float(kv.x) * pq2.x;
            float kp1 = __bfloat162float(kv.y) * pq2.y;
            const float4* ka0 = (const float4*)(skaw + c0 * KAP);
            const float4* ka1 = (const float4*)(skaw + (c0 + 1) * KAP);
            float4 a0 = ka0[0], a1 = ka0[1], b0 = ka1[0], b1 = ka1[1];
            acc[0] += kp0 * a0.x + kp1 * b0.x; acc[1] += kp0 * a0.y + kp1 * b0.y;
            acc[2] += kp0 * a0.z + kp1 * b0.z; acc[3] += kp0 * a0.w + kp1 * b0.w;
            acc[4] += kp0 * a1.x + kp1 * b1.x; acc[5] += kp0 * a1.y + kp1 * b1.y;
            acc[6] += kp0 * a1.z + kp1 * b1.z; acc[7] += kp0 * a1.w + kp1 * b1.w;
        }
#pragma unroll
        for (int o = 16; o >= 8; o >>= 1)
#pragma unroll
            for (int e = 0; e < 8; e++)
                acc[e] += __shfl_xor_sync(0xffffffffu, acc[e], o);
        if (lane < 8) {
#pragma unroll
            for (int e = 0; e < 8; e++) sred[half][wh][lane][e] = acc[e];
        }
        __syncwarp();
        if (lane < 8) {
            float s2 = 0.f;
#pragma unroll
            for (int m = 0; m < 8; m++) s2 += sred[half][wh][m][lane];
            skw[half][lane][l] = (s2 + kab) * kSCALE;
        }
        __syncwarp();
    }
    __syncthreads();

    // ---- k-weight softmax ----
#pragma unroll
    for (int hi = 0; hi < 2; hi++) {
        int hh = 2 * wh + hi;
        float lv[4]; float mx = -1e30f;
#pragma unroll
        for (int i = 0; i < 4; i++) {
            int l = lane + 32 * i;
            lv[i] = (l < kL) ? skw[half][hh][l] : -1e30f;
            mx = fmaxf(mx, lv[i]);
        }
#pragma unroll
        for (int o = 16; o; o >>= 1) mx = fmaxf(mx, __shfl_xor_sync(0xffffffffu, mx, o));
        float sm = 0.f;
#pragma unroll
        for (int i = 0; i < 4; i++) {
            int l = lane + 32 * i;
            lv[i] = (l < kL) ? expf(lv[i] - mx) : 0.f;
            sm += lv[i];
        }
#pragma unroll
        for (int o = 16; o; o >>= 1) sm += __shfl_xor_sync(0xffffffffu, sm, o);
        float inv = 1.f / sm;
#pragma unroll
        for (int i = 0; i < 4; i++) {
            int l = lane + 32 * i;
            if (l < kL) skw[half][hh][l] = lv[i] * inv;
        }
    }
    __syncthreads();

    // ---- pass C1: pk ----
    float pk0 = 0.f, pk1 = 0.f;
#pragma unroll 5
    for (int v = 0; v < kV; v++) {
#pragma unroll
        for (int w = 0; w < kWIN; w++) {
            int l = w * kV + v;
            float2 kv = bf2f(*(const uint32_t*)(g_qkvh + (size_t)su[half][l] * kC3 + 256 + 2 * ti));
            float sw = skw[half][hch][l];
            pk0 += sw * kv.x;
            pk1 += sw * kv.y;
        }
    }
    // ---- pass C2: mv -> mkv = pk*mv ----
#pragma unroll 5
    for (int v = 0; v < kV; v++) {
        float a0 = 0.f, a1 = 0.f;
#pragma unroll
        for (int w = 0; w < kWIN; w++) {
            float2 vv = bf2f(*(const uint32_t*)(g_qkvh + (size_t)su[half][w * kV + v] * kC3 + 512 + 2 * ti));
            a0 += vv.x;
            a1 += vv.y;
        }
        stcs_u32(g_mkvh + ((size_t)b * kV + v) * kC + 2 * ti,
                 f2bf2(pk0 * a0 * 0.2f, pk1 * a1 * 0.2f));
    }
}

// ===================================================================================
extern "C" void kernel_launch(void* const* d_in, const int* in_sizes, int n_in,
                              void* d_out, int out_size) {
    const float* x    = (const float*)d_in[0];
    const float* ln1g = (const float*)d_in[1];
    const float* ln1b = (const float*)d_in[2];
    const float* q_w  = (const float*)d_in[3];
    const float* q_b  = (const float*)d_in[4];
    const float* qa_w = (const float*)d_in[5];
    const float* qa_b = (const float*)d_in[6];
    const float* k_w  = (const float*)d_in[7];
    const float* k_b  = (const float*)d_in[8];
    const float* ka_w = (const float*)d_in[9];
    const float* ka_b = (const float*)d_in[10];
    const float* v_w  = (const float*)d_in[11];
    const float* v_b  = (const float*)d_in[12];
    const float* t_w  = (const float*)d_in[13];
    const float* t_b  = (const float*)d_in[14];
    const float* p_w  = (const float*)d_in[15];
    const float* p_b  = (const float*)d_in[16];
    const float* ffng = (const float*)d_in[17];
    const float* ffnb = (const float*)d_in[18];
    const float* w1   = (const float*)d_in[19];
    const float* b1   = (const float*)d_in[20];
    const float* w2   = (const float*)d_in[21];
    const float* b2   = (const float*)d_in[22];
    float* out = (float*)d_out;

    float *p_k, *p_xr, *p_tb, *p_qkvb;
    __nv_bfloat16 *p_nxh, *p_qkvh, *p_fh, *p_mkvh, *p_mqh, *p_h1h, *p_twT, *p_wqkvT, *p_wpT, *p_w1T, *p_w2T;
    cudaGetSymbolAddress((void**)&p_k,     g_k);
    cudaGetSymbolAddress((void**)&p_xr,    g_xr);
    cudaGetSymbolAddress((void**)&p_tb,    g_tb);
    cudaGetSymbolAddress((void**)&p_qkvb,  g_qkvb);
    cudaGetSymbolAddress((void**)&p_nxh,   g_nxh);
    cudaGetSymbolAddress((void**)&p_qkvh,  g_qkvh);
    cudaGetSymbolAddress((void**)&p_fh,    g_fh);
    cudaGetSymbolAddress((void**)&p_mkvh,  g_mkvh);
    cudaGetSymbolAddress((void**)&p_mqh,   g_mqh);
    cudaGetSymbolAddress((void**)&p_h1h,   g_h1h);
    cudaGetSymbolAddress((void**)&p_twT,   g_twT);
    cudaGetSymbolAddress((void**)&p_wqkvT, g_wqkvT);
    cudaGetSymbolAddress((void**)&p_wpT,   g_wpT);
    cudaGetSymbolAddress((void**)&p_w1T,   g_w1T);
    cudaGetSymbolAddress((void**)&p_w2T,   g_w2T);

    cudaFuncSetAttribute(k_gemm7<0,1>, cudaFuncAttributeMaxDynamicSharedMemorySize, GEMM_SMEM);
    cudaFuncSetAttribute(k_gemm7<2,1>, cudaFuncAttributeMaxDynamicSharedMemorySize, GEMM_SMEM);
    cudaFuncSetAttribute(k_gemm7<3,2>, cudaFuncAttributeMaxDynamicSharedMemorySize, GEMM_SMEM);
    cudaFuncSetAttribute(k_gemm7<4,1>, cudaFuncAttributeMaxDynamicSharedMemorySize, GEMM_SMEM);

    dim3 gqkv((kM1 + 127) / 128, 3);   // 401 x 3
    int g2 = kU / 128;                 // 400

    // 0) prep
    k_prep<<<257 + 384 + 3 + 1, 256>>>(t_w, p_w, t_b, p_b, q_w, k_w, v_w, w1, w2,
                                       q_b, k_b, v_b, qa_w, qa_b);
    // 1) LN -> bf16 nx + fp32 xr + fused qlog
    k_ln_x<<<(kM1 + 31) / 32, 256>>>(x, ln1g, ln1b);
    // 2) fused q|k|v projection -> g_qkvh bf16
    k_gemm7<0,1><<<gqkv, 512, GEMM_SMEM>>>(p_nxh, p_wqkvT, nullptr, nullptr, p_qkvb, nullptr,
                                           nullptr, p_qkvh, nullptr, nullptr, kM1, kC3);
    // 3) pooling v5 @ 4 CTA/SM
    k_pool<<<kB / 2, 256>>>(ka_w, ka_b);
    // 4) attraw = mkv@tp_w + mq@p_w + tp_b + xr -> g_k ; fused LN -> f bf16
    k_gemm7<3,2><<<g2, 512, GEMM_SMEM>>>(p_mkvh, p_twT, p_mqh, p_wpT, p_tb, p_xr,
                                         p_k, p_fh, ffng, ffnb, kU, kC);
    // 5) h1 = gelu(f @ w1 + b1) -> bf16
    k_gemm7<2,1><<<g2, 512, GEMM_SMEM>>>(p_fh, p_w1T, nullptr, nullptr, b1, nullptr,
                                         nullptr, p_h1h, nullptr, nullptr, kU, kC);
    // 6) y = h1 @ w2 + b2 + attraw -> transposed out
    k_gemm7<4,1><<<g2, 512, GEMM_SMEM>>>(p_h1h, p_w2T, nullptr, nullptr, b2, p_k,
                                         out, nullptr, nullptr, nullptr, kU, kC);
}

// round 17
// speedup vs baseline: 1.0556x; 1.0136x over previous
#include <cuda_runtime.h>
#include <cuda_bf16.h>
#include <cstdint>
#include <cstddef>

constexpr int kN   = 32;
constexpr int kC   = 256;
constexpr int kC3  = 768;
constexpr int kT   = 64;
constexpr int kV   = 25;
constexpr int kH   = 8;
constexpr int kWIN = 5;
constexpr int kB   = kN * kT;        // 2048 windows
constexpr int kL   = kWIN * kV;      // 125
constexpr int kU   = kB * kV;        // 51200 unique tokens
constexpr int kM1  = kU + 1;         // + pad row
constexpr int kTV  = kT * kV;        // 1600
constexpr int kXN  = kC * kTV;       // 409600
constexpr float kSCALE = 0.17677669529663687f;  // 1/sqrt(32)

// ---------------- scratch ----------------
__device__ __nv_bfloat16 g_nxh [(size_t)kM1 * kC];
__device__ __nv_bfloat16 g_qkvh[(size_t)kM1 * kC3];
__device__ float         g_k   [(size_t)kM1 * kC];
__device__ __nv_bfloat16 g_fh  [(size_t)kU  * kC];
__device__ float         g_xr  [(size_t)kU  * kC];
__device__ __nv_bfloat16 g_mkvh[(size_t)kU  * kC];
__device__ __nv_bfloat16 g_mqh [(size_t)kU  * kC];
__device__ __nv_bfloat16 g_h1h [(size_t)kU  * kC];
__device__ float         g_ql  [(size_t)kM1 * kH];
__device__ __nv_bfloat16 g_twT [65536];
__device__ float         g_tb  [kC];
__device__ __nv_bfloat16 g_wqkvT[(size_t)kC3 * kC];
__device__ __nv_bfloat16 g_wpT [65536];
__device__ __nv_bfloat16 g_w1T [65536];
__device__ __nv_bfloat16 g_w2T [65536];
__device__ float         g_qkvb[kC3];
__device__ float         g_qaw [kC * kH];
__device__ float         g_qab [kH];

__device__ __forceinline__ void stcs_u32(void* p, uint32_t v) {
    asm volatile("st.global.cs.b32 [%0], %1;" :: "l"(p), "r"(v));
}
__device__ __forceinline__ float2 bf2f(uint32_t u) {
    __nv_bfloat162 h = *(__nv_bfloat162*)&u;
    return make_float2(__bfloat162float(h.x), __bfloat162float(h.y));
}
__device__ __forceinline__ uint32_t f2bf2(float a, float b) {
    __nv_bfloat162 h = {__float2bfloat16(a), __float2bfloat16(b)};
    return *(uint32_t*)&h;
}

// ============ prep ============
__global__ void __launch_bounds__(256) k_prep(const float* __restrict__ t_w,
                                              const float* __restrict__ p_w,
                                              const float* __restrict__ t_b,
                                              const float* __restrict__ p_b,
                                              const float* __restrict__ q_w,
                                              const float* __restrict__ k_w,
                                              const float* __restrict__ v_w,
                                              const float* __restrict__ w1,
                                              const float* __restrict__ w2,
                                              const float* __restrict__ q_b,
                                              const float* __restrict__ k_b,
                                              const float* __restrict__ v_b,
                                              const float* __restrict__ qa_w,
                                              const float* __restrict__ qa_b) {
    int bid = blockIdx.x, tid = threadIdx.x;
    if (bid < 257) {
        __shared__ float srow[kC];
        bool isw = (bid < kC);
        srow[tid] = isw ? t_w[(size_t)bid * kC + tid] : t_b[tid];
        __syncthreads();
        float acc = isw ? 0.f : p_b[tid];
#pragma unroll 8
        for (int m = 0; m < kC; m++) acc += srow[m] * p_w[(size_t)m * kC + tid];
        if (isw) g_twT[(size_t)tid * kC + bid] = __float2bfloat16(acc);
        else     g_tb[tid] = acc;
    } else if (bid < 257 + 384) {
        __shared__ float tile[32][33];
        int t = bid - 257;
        int w = t >> 6; t &= 63;
        int k0 = (t >> 3) * 32, n0 = (t & 7) * 32;
        const float* s = (w == 0) ? q_w : (w == 1) ? k_w : (w == 2) ? v_w
                       : (w == 3) ? p_w : (w == 4) ? w1 : w2;
        __nv_bfloat16* dT = (w < 3) ? (g_wqkvT + (size_t)w * 256 * kC)
                          : (w == 3) ? g_wpT : (w == 4) ? g_w1T : g_w2T;
        int tx = tid & 31, ty = tid >> 5;
#pragma unroll
        for (int j = 0; j < 4; j++)
            tile[ty + 8 * j][tx] = s[(size_t)(k0 + ty + 8 * j) * kC + n0 + tx];
        __syncthreads();
#pragma unroll
        for (int j = 0; j < 4; j++)
            dT[(size_t)(n0 + ty + 8 * j) * kC + k0 + tx] = __float2bfloat16(tile[tx][ty + 8 * j]);
    } else if (bid < 257 + 384 + 3) {
        int k = bid - (257 + 384);
        g_qkvb[k * 256 + tid] = (k == 0) ? q_b[tid] : (k == 1) ? k_b[tid] : v_b[tid];
    } else {
        __shared__ float sqa[kC][kH];
        for (int i = tid; i < kC * kH; i += 256) sqa[i >> 3][i & 7] = qa_w[i];
        __syncthreads();
        int c = tid;
        float acc[8] = {};
        const float* qr = q_w + (size_t)c * kC;
#pragma unroll 4
        for (int j = 0; j < kC; j++) {
            float qv = qr[j];
#pragma unroll
            for (int e = 0; e < 8; e++) acc[e] += qv * sqa[j][e];
        }
#pragma unroll
        for (int e = 0; e < 8; e++) g_qaw[c * kH + e] = acc[e];
        if (tid < kH) {
            float a = qa_b[tid];
            for (int j = 0; j < kC; j++) a += q_b[j] * sqa[j][tid];
            g_qab[tid] = a;
        }
    }
}

// ============ LN of unique tokens -> bf16 nx, raw xr (.cs), fused qlog ============
__global__ void __launch_bounds__(256) k_ln_x(const float* __restrict__ x,
                                              const float* __restrict__ g,
                                              const float* __restrict__ b) {
    __shared__ float sx[32][257];
    int tid = threadIdx.x;
    int u0  = blockIdx.x * 32;
    {
        int ur = tid & 31;
        int u  = u0 + ur;
        int cb = tid >> 5;
        bool has = (u < kU);
        size_t base = 0;
        if (has) { int n = u / kTV; base = (size_t)n * kXN + (u - n * kTV); }
#pragma unroll
        for (int j = 0; j < 32; j++) {
            int c = cb * 32 + j;
            sx[ur][c] = has ? x[base + (size_t)c * kTV] : 0.f;
        }
    }
    __syncthreads();
    int lane = tid & 31, warp = tid >> 5;
    float wreg[8][8];
#pragma unroll
    for (int j = 0; j < 8; j++) {
        const float4* wr = (const float4*)(g_qaw + (size_t)(lane + 32 * j) * kH);
        float4 w0 = wr[0], w1 = wr[1];
        wreg[j][0] = w0.x; wreg[j][1] = w0.y; wreg[j][2] = w0.z; wreg[j][3] = w0.w;
        wreg[j][4] = w1.x; wreg[j][5] = w1.y; wreg[j][6] = w1.z; wreg[j][7] = w1.w;
    }
    float qab = (lane < kH) ? g_qab[lane] : 0.f;
#pragma unroll 1
    for (int rr = 0; rr < 4; rr++) {
        int ur = warp * 4 + rr;
        int u  = u0 + ur;
        if (u >= kM1) continue;
        float vals[8];
        float s = 0.f, sq = 0.f;
#pragma unroll
        for (int j = 0; j < 8; j++) {
            float t = sx[ur][lane + 32 * j];
            vals[j] = t; s += t; sq += t * t;
        }
#pragma unroll
        for (int o = 16; o; o >>= 1) {
            s  += __shfl_xor_sync(0xffffffffu, s,  o);
            sq += __shfl_xor_sync(0xffffffffu, sq, o);
        }
        float mean = s * (1.f / kC);
        float var  = sq * (1.f / kC) - mean * mean;
        float rstd = rsqrtf(var + 1e-5f);
        float acc[8] = {};
#pragma unroll
        for (int j = 0; j < 8; j++) {
            int c = lane + 32 * j;
            float nv = (vals[j] - mean) * rstd * g[c] + b[c];
            g_nxh[(size_t)u * kC + c] = __float2bfloat16(nv);
            if (u < kU) __stcs(g_xr + (size_t)u * kC + c, vals[j]);
#pragma unroll
            for (int e = 0; e < 8; e++) acc[e] += nv * wreg[j][e];
        }
#pragma unroll
        for (int o = 16; o; o >>= 1)
#pragma unroll
            for (int e = 0; e < 8; e++)
                acc[e] += __shfl_xor_sync(0xffffffffu, acc[e], o);
        if (lane < kH) g_ql[(size_t)u * kH + lane] = (acc[lane] + qab) * kSCALE;
    }
}

// ============ shared GEMM helpers ============
constexpr int HP   = 40;
__device__ __forceinline__ void mma_bf16(float (&d)[4], const uint32_t (&a)[4],
                                         const uint32_t (&bb)[2]) {
    asm volatile(
        "mma.sync.aligned.m16n8k16.row.col.f32.bf16.bf16.f32 "
        "{%0,%1,%2,%3}, {%4,%5,%6,%7}, {%8,%9}, {%0,%1,%2,%3};\n"
        : "+f"(d[0]), "+f"(d[1]), "+f"(d[2]), "+f"(d[3])
        : "r"(a[0]), "r"(a[1]), "r"(a[2]), "r"(a[3]), "r"(bb[0]), "r"(bb[1]));
}
__device__ __forceinline__ void cpa16(uint32_t dst, const void* src, bool pred) {
    int sz = pred ? 16 : 0;
    asm volatile("cp.async.cg.shared.global [%0], [%1], 16, %2;\n"
                 :: "r"(dst), "l"(src), "r"(sz));
}
__device__ __forceinline__ float gelu_exact(float x) {
    return 0.5f * x * (1.0f + erff(x * 0.70710678118654752f));
}

// ============ bf16 GEMM7: CTA 128x256, 512 thr (EPI 3 / 4 only) ============
constexpr int ASZH = 128 * HP;
constexpr int BSZH = 256 * HP;
constexpr int GEMM_SMEM = 3 * (ASZH + BSZH) * 2;
constexpr int BPITCH = 264;

template<int EPI, int NPAIR>
__global__ void __launch_bounds__(512, 1) k_gemm7(const __nv_bfloat16* __restrict__ A1,
                                                  const __nv_bfloat16* __restrict__ W1,
                                                  const __nv_bfloat16* __restrict__ A2,
                                                  const __nv_bfloat16* __restrict__ W2,
                                                  const float* __restrict__ bias,
                                                  const float* __restrict__ addm,
                                                  float* __restrict__ D,
                                                  __nv_bfloat16* __restrict__ Dh,
                                                  const float* __restrict__ lng,
                                                  const float* __restrict__ lnb,
                                                  int M, int ldD) {
    extern __shared__ char smc[];
    __nv_bfloat16* As = (__nv_bfloat16*)smc;
    __nv_bfloat16* Bs = As + 3 * ASZH;
    float* ep = (float*)smc;
    uint32_t sA = (uint32_t)__cvta_generic_to_shared(As);
    uint32_t sB = (uint32_t)__cvta_generic_to_shared(Bs);

    int tid = threadIdx.x, lane = tid & 31, warp = tid >> 5;
    int wm = warp >> 2, wn = warp & 3;
    int p = lane >> 2, q = lane & 3;
    int row0 = blockIdx.x * 128;
    int mbase = wm * 32, nbase = wn * 64;

    int ar = tid & 127, ah = tid >> 7;
    int bn = tid & 255, bh = tid >> 8;
    bool arow_ok = (row0 + ar) < M;
    const __nv_bfloat16* A1g = A1 + (size_t)(row0 + ar) * kC + ah * 8;
    const __nv_bfloat16* W1g = W1 + (size_t)bn * kC + bh * 16;
    const __nv_bfloat16* A2g = (NPAIR == 2) ? (A2 + (size_t)(row0 + ar) * kC + ah * 8) : A1g;
    const __nv_bfloat16* W2g = (NPAIR == 2) ? (W2 + (size_t)bn * kC + bh * 16) : W1g;
    uint32_t adst0 = sA + (uint32_t)((ar * HP + ah * 8) * 2);
    uint32_t bdst0 = sB + (uint32_t)((bn * HP + bh * 16) * 2);

    auto issue = [&](int kt) {
        int ktt = kt & 7;
        int buf = kt % 3;
        const __nv_bfloat16* as = ((NPAIR == 2 && (kt >> 3)) ? A2g : A1g) + ktt * 32;
        const __nv_bfloat16* bs = ((NPAIR == 2 && (kt >> 3)) ? W2g : W1g) + ktt * 32;
        cpa16(adst0 + (uint32_t)(buf * ASZH * 2), as, arow_ok);
        uint32_t bd = bdst0 + (uint32_t)(buf * BSZH * 2);
        cpa16(bd,      bs,     true);
        cpa16(bd + 16, bs + 8, true);
    };

    float acc[2][8][4] = {};
    const int TOT = 8 * NPAIR;

    issue(0);
    asm volatile("cp.async.commit_group;\n");
    issue(1);
    asm volatile("cp.async.commit_group;\n");

#pragma unroll 1
    for (int kt = 0; kt < TOT; kt++) {
        if (kt < TOT - 1) asm volatile("cp.async.wait_group 1;\n");
        else              asm volatile("cp.async.wait_group 0;\n");
        __syncthreads();
        if (kt + 2 < TOT) {
            issue(kt + 2);
            asm volatile("cp.async.commit_group;\n");
        }
        int buf = kt % 3;
        const __nv_bfloat16* Ab = As + buf * ASZH;
        const __nv_bfloat16* Bb = Bs + buf * BSZH;
#pragma unroll
        for (int kk = 0; kk < 32; kk += 16) {
            uint32_t af[2][4], bf[8][2];
#pragma unroll
            for (int mi = 0; mi < 2; mi++) {
                const __nv_bfloat16* a0 = Ab + (mbase + mi * 16 + p) * HP + kk + 2 * q;
                af[mi][0] = *(const uint32_t*)(a0);
                af[mi][1] = *(const uint32_t*)(a0 + 8 * HP);
                af[mi][2] = *(const uint32_t*)(a0 + 8);
                af[mi][3] = *(const uint32_t*)(a0 + 8 * HP + 8);
            }
#pragma unroll
            for (int ni = 0; ni < 8; ni++) {
                const __nv_bfloat16* b0 = Bb + (nbase + ni * 8 + p) * HP + kk + 2 * q;
                bf[ni][0] = *(const uint32_t*)(b0);
                bf[ni][1] = *(const uint32_t*)(b0 + 8);
            }
#pragma unroll
            for (int mi = 0; mi < 2; mi++)
#pragma unroll
                for (int ni = 0; ni < 8; ni++)
                    mma_bf16(acc[mi][ni], af[mi], bf[ni]);
        }
    }
    __syncthreads();

#pragma unroll 1
    for (int half = 0; half < 2; half++) {
        __syncthreads();
        if ((wm >> 1) == half) {
#pragma unroll
            for (int mi = 0; mi < 2; mi++) {
                int lr1 = mbase + mi * 16 + p;
                int lr2 = lr1 + 8;
                int r1 = row0 + lr1, r2 = row0 + lr2;
                int e1 = lr1 - half * 64, e2 = lr2 - half * 64;
#pragma unroll
                for (int ni = 0; ni < 8; ni++) {
                    int cc = nbase + ni * 8 + 2 * q;
                    float2 bv = *(const float2*)(bias + cc);
                    float2 a1 = *(const float2*)(addm + (size_t)r1 * kC + cc);
                    float2 a2 = *(const float2*)(addm + (size_t)r2 * kC + cc);
                    float2 o1 = {acc[mi][ni][0] + bv.x + a1.x, acc[mi][ni][1] + bv.y + a1.y};
                    float2 o2 = {acc[mi][ni][2] + bv.x + a2.x, acc[mi][ni][3] + bv.y + a2.y};
                    if (EPI == 3) {
                        *(float2*)(D + (size_t)r1 * ldD + cc) = o1;
                        *(float2*)(D + (size_t)r2 * ldD + cc) = o2;
                    }
                    *(float2*)(ep + e1 * BPITCH + cc) = o1;
                    *(float2*)(ep + e2 * BPITCH + cc) = o2;
                }
            }
        }
        __syncthreads();
        if (EPI == 3) {
            float gg[8], bb[8];
#pragma unroll
            for (int j = 0; j < 8; j++) {
                int c = lane + 32 * j;
                gg[j] = lng[c]; bb[j] = lnb[c];
            }
#pragma unroll
            for (int rr = 0; rr < 4; rr++) {
                int lr = warp * 4 + rr;
                float vals[8]; float s = 0.f, sq = 0.f;
#pragma unroll
                for (int j = 0; j < 8; j++) {
                    float t = ep[lr * BPITCH + lane + 32 * j];
                    vals[j] = t; s += t; sq += t * t;
                }
#pragma unroll
                for (int o = 16; o; o >>= 1) {
                    s  += __shfl_xor_sync(0xffffffffu, s,  o);
                    sq += __shfl_xor_sync(0xffffffffu, sq, o);
                }
                float mean = s * (1.f / kC);
                float var  = sq * (1.f / kC) - mean * mean;
                float rstd = rsqrtf(var + 1e-5f);
                int gr = row0 + half * 64 + lr;
#pragma unroll
                for (int j = 0; j < 8; j++) {
                    int c = lane + 32 * j;
                    Dh[(size_t)gr * kC + c] = __float2bfloat16((vals[j] - mean) * rstd * gg[j] + bb[j]);
                }
            }
        } else {
#pragma unroll 1
            for (int it = 0; it < 32; it++) {
                int j = it * 512 + tid;
                int c = j >> 6, rr = j & 63;
                unsigned R = (unsigned)(row0 + half * 64 + rr);
                unsigned b = R / 25u;
                unsigned v = R - b * 25u;
                unsigned n = b >> 6, t = b & 63u;
                D[(size_t)n * kXN + (size_t)c * kTV + t * kV + v] = ep[rr * BPITCH + c];
            }
        }
    }
}

// ============ bf16 GEMM8: CTA 128x128, 256 thr, 3-stage, 2 CTA/SM (EPI 0 / 2) ============
constexpr int A8SZ = 128 * HP;
constexpr int B8SZ = 128 * HP;
constexpr int GEMM8_SMEM = 3 * (A8SZ + B8SZ) * 2;   // 61440 bytes

template<int EPI>
__global__ void __launch_bounds__(256, 2) k_gemm8(const __nv_bfloat16* __restrict__ A,
                                                  const __nv_bfloat16* __restrict__ W,
                                                  const float* __restrict__ bias,
                                                  __nv_bfloat16* __restrict__ Dh,
                                                  int M, int ldD) {
    extern __shared__ char smc[];
    __nv_bfloat16* As = (__nv_bfloat16*)smc;
    __nv_bfloat16* Bs = As + 3 * A8SZ;
    uint32_t sA = (uint32_t)__cvta_generic_to_shared(As);
    uint32_t sB = (uint32_t)__cvta_generic_to_shared(Bs);

    int coly = blockIdx.y * 128;
    bias += coly; Dh += coly;

    int tid = threadIdx.x, lane = tid & 31, warp = tid >> 5;
    int wm = warp >> 1, wn = warp & 1;       // 4 x 2 warp grid, warp tile 32x64
    int p = lane >> 2, q = lane & 3;
    int row0 = blockIdx.x * 128;
    int mbase = wm * 32, nbase = wn * 64;

    int r = tid & 127, hk = (tid >> 7) * 16; // row, k-offset (0 or 16)
    bool arow_ok = (row0 + r) < M;
    const __nv_bfloat16* Ag = A + (size_t)(row0 + r) * kC + hk;
    const __nv_bfloat16* Wg = W + (size_t)(coly + r) * kC + hk;
    uint32_t adst0 = sA + (uint32_t)((r * HP + hk) * 2);
    uint32_t bdst0 = sB + (uint32_t)((r * HP + hk) * 2);

    auto issue = [&](int kt) {
        int buf = kt % 3;
        const __nv_bfloat16* as = Ag + kt * 32;
        const __nv_bfloat16* bs = Wg + kt * 32;
        uint32_t ad = adst0 + (uint32_t)(buf * A8SZ * 2);
        uint32_t bd = bdst0 + (uint32_t)(buf * B8SZ * 2);
        cpa16(ad,      as,     arow_ok);
        cpa16(ad + 16, as + 8, arow_ok);
        cpa16(bd,      bs,     true);
        cpa16(bd + 16, bs + 8, true);
    };

    float acc[2][8][4] = {};

    issue(0);
    asm volatile("cp.async.commit_group;\n");
    issue(1);
    asm volatile("cp.async.commit_group;\n");

#pragma unroll 1
    for (int kt = 0; kt < 8; kt++) {
        if (kt < 7) asm volatile("cp.async.wait_group 1;\n");
        else        asm volatile("cp.async.wait_group 0;\n");
        __syncthreads();
        if (kt + 2 < 8) {
            issue(kt + 2);
            asm volatile("cp.async.commit_group;\n");
        }
        int buf = kt % 3;
        const __nv_bfloat16* Ab = As + buf * A8SZ;
        const __nv_bfloat16* Bb = Bs + buf * B8SZ;
#pragma unroll
        for (int kk = 0; kk < 32; kk += 16) {
            uint32_t af[2][4], bf[8][2];
#pragma unroll
            for (int mi = 0; mi < 2; mi++) {
                const __nv_bfloat16* a0 = Ab + (mbase + mi * 16 + p) * HP + kk + 2 * q;
                af[mi][0] = *(const uint32_t*)(a0);
                af[mi][1] = *(const uint32_t*)(a0 + 8 * HP);
                af[mi][2] = *(const uint32_t*)(a0 + 8);
                af[mi][3] = *(const uint32_t*)(a0 + 8 * HP + 8);
            }
#pragma unroll
            for (int ni = 0; ni < 8; ni++) {
                const __nv_bfloat16* b0 = Bb + (nbase + ni * 8 + p) * HP + kk + 2 * q;
                bf[ni][0] = *(const uint32_t*)(b0);
                bf[ni][1] = *(const uint32_t*)(b0 + 8);
            }
#pragma unroll
            for (int mi = 0; mi < 2; mi++)
#pragma unroll
                for (int ni = 0; ni < 8; ni++)
                    mma_bf16(acc[mi][ni], af[mi], bf[ni]);
        }
    }

#pragma unroll
    for (int mi = 0; mi < 2; mi++) {
        int r1 = row0 + mbase + mi * 16 + p;
        int r2 = r1 + 8;
#pragma unroll
        for (int ni = 0; ni < 8; ni++) {
            int cc = nbase + ni * 8 + 2 * q;
            float2 bv = *(const float2*)(bias + cc);
            float d0 = acc[mi][ni][0] + bv.x, d1 = acc[mi][ni][1] + bv.y;
            float d2 = acc[mi][ni][2] + bv.x, d3 = acc[mi][ni][3] + bv.y;
            if (EPI == 2) {
                d0 = gelu_exact(d0); d1 = gelu_exact(d1);
                d2 = gelu_exact(d2); d3 = gelu_exact(d3);
            }
            __nv_bfloat162 o1 = {__float2bfloat16(d0), __float2bfloat16(d1)};
            __nv_bfloat162 o2 = {__float2bfloat16(d2), __float2bfloat16(d3)};
            if (r1 < M) *(__nv_bfloat162*)(Dh + (size_t)r1 * ldD + cc) = o1;
            if (r2 < M) *(__nv_bfloat162*)(Dh + (size_t)r2 * ldD + cc) = o2;
        }
    }
}

// ============ pool v5 @ 4 CTA/SM (unchanged from R16) ============
constexpr int KAP = 12;
__global__ void __launch_bounds__(256, 4) k_pool(const float* __restrict__ ka_w,
                                                 const float* __restrict__ ka_b) {
    __shared__ int   su[2][kL];
    __shared__ float sqw[2][kH][128];
    __shared__ float skw[2][kH][128];
    __shared__ float spq[2][kC];
    __shared__ __align__(16) float skaw[kC * KAP];
    __shared__ float sred[2][4][kH][9];
    int tid = threadIdx.x, lane = tid & 31;
    int half = tid >> 7;
    int ti = tid & 127;
    int wh = ti >> 5;
    int b = (gridDim.x - 1 - blockIdx.x) * 2 + half;
    int n = b / kT, t = b % kT;
    int hch = ti >> 4;

    for (int i = tid; i < kC * kH; i += 256) {
        int c = i >> 3, e = i & 7;
        skaw[c * KAP + e] = ka_w[i];
    }
    if (ti < kL) {
        int w = ti / kV, v = ti - w * kV;
        int tp = t + w - 2;
        su[half][ti] = (tp >= 0 && tp < kT) ? (n * kT + tp) * kV + v : kU;
    }
    float kab = (lane < kH) ? ka_b[lane] : 0.f;
    __syncthreads();

#pragma unroll
    for (int hi = 0; hi < 2; hi++) {
        int hh = 2 * wh + hi;
        float lv[4]; float mx = -1e30f;
#pragma unroll
        for (int i = 0; i < 4; i++) {
            int l = lane + 32 * i;
            lv[i] = (l < kL) ? g_ql[(size_t)su[half][l] * kH + hh] : -1e30f;
            mx = fmaxf(mx, lv[i]);
        }
#pragma unroll
        for (int o = 16; o; o >>= 1) mx = fmaxf(mx, __shfl_xor_sync(0xffffffffu, mx, o));
        float sm = 0.f;
#pragma unroll
        for (int i = 0; i < 4; i++) {
            int l = lane + 32 * i;
            lv[i] = (l < kL) ? expf(lv[i] - mx) : 0.f;
            sm += lv[i];
        }
#pragma unroll
        for (int o = 16; o; o >>= 1) sm += __shfl_xor_sync(0xffffffffu, sm, o);
        float inv = 1.f / sm;
#pragma unroll
        for (int i = 0; i < 4; i++) {
            int l = lane + 32 * i;
            if (l < kL) sqw[half][hh][l] = lv[i] * inv;
        }
    }
    __syncthreads();

    float pq0 = 0.f, pq1 = 0.f;
#pragma unroll 5
    for (int v = 0; v < kV; v++) {
        float a0 = 0.f, a1 = 0.f;
#pragma unroll
        for (int w = 0; w < kWIN; w++) {
            int l = w * kV + v;
            float2 xv = bf2f(*(const uint32_t*)(g_qkvh + (size_t)su[half][l] * kC3 + 2 * ti));
            float sw = sqw[half][hch][l];
            pq0 += sw * xv.x; pq1 += sw * xv.y;
            a0 += xv.x; a1 += xv.y;
        }
        stcs_u32(g_mqh + ((size_t)b * kV + v) * kC + 2 * ti, f2bf2(a0 * 0.2f, a1 * 0.2f));
    }
    spq[half][2 * ti]     = pq0;
    spq[half][2 * ti + 1] = pq1;
    __syncthreads();

#pragma unroll 1
    for (int l = wh; l < kL; l += 4) {
        const __nv_bfloat16* kr = g_qkvh + (size_t)su[half][l] * kC3 + 256;
        float acc[8] = {};
#pragma unroll
        for (int j = 0; j < 4; j++) {
            int cp = lane + 32 * j;
            int c0 = 2 * cp;
            __nv_bfloat162 kv = *(const __nv_bfloat162*)(kr + c0);
            float2 pq2 = *(const float2*)(spq[half] + c0);
            float kp0 = __bfloat162float(kv.x) * pq2.x;
            float kp1 = __bfloat162float(kv.y) * pq2.y;
            const float4* ka0 = (const float4*)(skaw + c0 * KAP);
            const float4* ka1 = (const float4*)(skaw + (c0 + 1) * KAP);
            float4 a0 = ka0[0], a1 = ka0[1], b0 = ka1[0], b1 = ka1[1];
            acc[0] += kp0 * a0.x + kp1 * b0.x; acc[1] += kp0 * a0.y + kp1 * b0.y;
            acc[2] += kp0 * a0.z + kp1 * b0.z; acc[3] += kp0 * a0.w + kp1 * b0.w;
            acc[4] += kp0 * a1.x + kp1 * b1.x; acc[5] += kp0 * a1.y + kp1 * b1.y;
            acc[6] += kp0 * a1.z + kp1 * b1.z; acc[7] += kp0 * a1.w + kp1 * b1.w;
        }
#pragma unroll
        for (int o = 16; o >= 8; o >>= 1)
#pragma unroll
            for (int e = 0; e < 8; e++)
                acc[e] += __shfl_xor_sync(0xffffffffu, acc[e], o);
        if (lane < 8) {
#pragma unroll
            for (int e = 0; e < 8; e++) sred[half][wh][lane][e] = acc[e];
        }
        __syncwarp();
        if (lane < 8) {
            float s2 = 0.f;
#pragma unroll
            for (int m = 0; m < 8; m++) s2 += sred[half][wh][m][lane];
            skw[half][lane][l] = (s2 + kab) * kSCALE;
        }
        __syncwarp();
    }
    __syncthreads();

#pragma unroll
    for (int hi = 0; hi < 2; hi++) {
        int hh = 2 * wh + hi;
        float lv[4]; float mx = -1e30f;
#pragma unroll
        for (int i = 0; i < 4; i++) {
            int l = lane + 32 * i;
            lv[i] = (l < kL) ? skw[half][hh][l] : -1e30f;
            mx = fmaxf(mx, lv[i]);
        }
#pragma unroll
        for (int o = 16; o; o >>= 1) mx = fmaxf(mx, __shfl_xor_sync(0xffffffffu, mx, o));
        float sm = 0.f;
#pragma unroll
        for (int i = 0; i < 4; i++) {
            int l = lane + 32 * i;
            lv[i] = (l < kL) ? expf(lv[i] - mx) : 0.f;
            sm += lv[i];
        }
#pragma unroll
        for (int o = 16; o; o >>= 1) sm += __shfl_xor_sync(0xffffffffu, sm, o);
        float inv = 1.f / sm;
#pragma unroll
        for (int i = 0; i < 4; i++) {
            int l = lane + 32 * i;
            if (l < kL) skw[half][hh][l] = lv[i] * inv;
        }
    }
    __syncthreads();

    float pk0 = 0.f, pk1 = 0.f;
#pragma unroll 5
    for (int v = 0; v < kV; v++) {
#pragma unroll
        for (int w = 0; w < kWIN; w++) {
            int l = w * kV + v;
            float2 kv = bf2f(*(const uint32_t*)(g_qkvh + (size_t)su[half][l] * kC3 + 256 + 2 * ti));
            float sw = skw[half][hch][l];
            pk0 += sw * kv.x;
            pk1 += sw * kv.y;
        }
    }
#pragma unroll 5
    for (int v = 0; v < kV; v++) {
        float a0 = 0.f, a1 = 0.f;
#pragma unroll
        for (int w = 0; w < kWIN; w++) {
            float2 vv = bf2f(*(const uint32_t*)(g_qkvh + (size_t)su[half][w * kV + v] * kC3 + 512 + 2 * ti));
            a0 += vv.x;
            a1 += vv.y;
        }
        stcs_u32(g_mkvh + ((size_t)b * kV + v) * kC + 2 * ti,
                 f2bf2(pk0 * a0 * 0.2f, pk1 * a1 * 0.2f));
    }
}

// ===================================================================================
extern "C" void kernel_launch(void* const* d_in, const int* in_sizes, int n_in,
                              void* d_out, int out_size) {
    const float* x    = (const float*)d_in[0];
    const float* ln1g = (const float*)d_in[1];
    const float* ln1b = (const float*)d_in[2];
    const float* q_w  = (const float*)d_in[3];
    const float* q_b  = (const float*)d_in[4];
    const float* qa_w = (const float*)d_in[5];
    const float* qa_b = (const float*)d_in[6];
    const float* k_w  = (const float*)d_in[7];
    const float* k_b  = (const float*)d_in[8];
    const float* ka_w = (const float*)d_in[9];
    const float* ka_b = (const float*)d_in[10];
    const float* v_w  = (const float*)d_in[11];
    const float* v_b  = (const float*)d_in[12];
    const float* t_w  = (const float*)d_in[13];
    const float* t_b  = (const float*)d_in[14];
    const float* p_w  = (const float*)d_in[15];
    const float* p_b  = (const float*)d_in[16];
    const float* ffng = (const float*)d_in[17];
    const float* ffnb = (const float*)d_in[18];
    const float* w1   = (const float*)d_in[19];
    const float* b1   = (const float*)d_in[20];
    const float* w2   = (const float*)d_in[21];
    const float* b2   = (const float*)d_in[22];
    float* out = (float*)d_out;

    float *p_k, *p_xr, *p_tb, *p_qkvb;
    __nv_bfloat16 *p_nxh, *p_qkvh, *p_fh, *p_mkvh, *p_mqh, *p_h1h, *p_twT, *p_wqkvT, *p_wpT, *p_w1T, *p_w2T;
    cudaGetSymbolAddress((void**)&p_k,     g_k);
    cudaGetSymbolAddress((void**)&p_xr,    g_xr);
    cudaGetSymbolAddress((void**)&p_tb,    g_tb);
    cudaGetSymbolAddress((void**)&p_qkvb,  g_qkvb);
    cudaGetSymbolAddress((void**)&p_nxh,   g_nxh);
    cudaGetSymbolAddress((void**)&p_qkvh,  g_qkvh);
    cudaGetSymbolAddress((void**)&p_fh,    g_fh);
    cudaGetSymbolAddress((void**)&p_mkvh,  g_mkvh);
    cudaGetSymbolAddress((void**)&p_mqh,   g_mqh);
    cudaGetSymbolAddress((void**)&p_h1h,   g_h1h);
    cudaGetSymbolAddress((void**)&p_twT,   g_twT);
    cudaGetSymbolAddress((void**)&p_wqkvT, g_wqkvT);
    cudaGetSymbolAddress((void**)&p_wpT,   g_wpT);
    cudaGetSymbolAddress((void**)&p_w1T,   g_w1T);
    cudaGetSymbolAddress((void**)&p_w2T,   g_w2T);

    cudaFuncSetAttribute(k_gemm7<3,2>, cudaFuncAttributeMaxDynamicSharedMemorySize, GEMM_SMEM);
    cudaFuncSetAttribute(k_gemm7<4,1>, cudaFuncAttributeMaxDynamicSharedMemorySize, GEMM_SMEM);
    cudaFuncSetAttribute(k_gemm8<0>,   cudaFuncAttributeMaxDynamicSharedMemorySize, GEMM8_SMEM);
    cudaFuncSetAttribute(k_gemm8<2>,   cudaFuncAttributeMaxDynamicSharedMemorySize, GEMM8_SMEM);

    dim3 gqkv((kM1 + 127) / 128, 6);   // 401 x 6 slabs of 128
    dim3 gh1(kU / 128, 2);             // 400 x 2
    int g2 = kU / 128;                 // 400

    // 0) prep
    k_prep<<<257 + 384 + 3 + 1, 256>>>(t_w, p_w, t_b, p_b, q_w, k_w, v_w, w1, w2,
                                       q_b, k_b, v_b, qa_w, qa_b);
    // 1) LN -> bf16 nx + fp32 xr + fused qlog
    k_ln_x<<<(kM1 + 31) / 32, 256>>>(x, ln1g, ln1b);
    // 2) fused q|k|v projection -> g_qkvh bf16 (2 CTA/SM GEMM)
    k_gemm8<0><<<gqkv, 256, GEMM8_SMEM>>>(p_nxh, p_wqkvT, p_qkvb, p_qkvh, kM1, kC3);
    // 3) pooling v5 @ 4 CTA/SM
    k_pool<<<kB / 2, 256>>>(ka_w, ka_b);
    // 4) attraw = mkv@tp_w + mq@p_w + tp_b + xr -> g_k ; fused LN -> f bf16
    k_gemm7<3,2><<<g2, 512, GEMM_SMEM>>>(p_mkvh, p_twT, p_mqh, p_wpT, p_tb, p_xr,
                                         p_k, p_fh, ffng, ffnb, kU, kC);
    // 5) h1 = gelu(f @ w1 + b1) -> bf16 (2 CTA/SM GEMM)
    k_gemm8<2><<<gh1, 256, GEMM8_SMEM>>>(p_fh, p_w1T, b1, p_h1h, kU, kC);
    // 6) y = h1 @ w2 + b2 + attraw -> transposed out
    k_gemm7<4,1><<<g2, 512, GEMM_SMEM>>>(p_h1h, p_w2T, nullptr, nullptr, b2, p_k,
                                         out, nullptr, nullptr, nullptr, kU, kC);
}